// round 8
// baseline (speedup 1.0000x reference)
#include <cuda_runtime.h>

// Problem constants
#define Bn    8
#define NN    2048
#define FINx  512
#define FOUTx 256
#define MTOT  (Bn*NN)          // 16384
#define ALPHAc 0.2f
#define NEGc  (-9e15f)

// ---------------- scratch (device globals: allocation-free) ----------------
__device__ float g_h [MTOT*FOUTx];            // feat@W
__device__ float g_h1[MTOT*FOUTx];            // feat@W1
__device__ float g_g [MTOT*FOUTx];            // h@a12
__device__ float g_h2[MTOT*FOUTx];            // fa@W2
__device__ float g_Ax[MTOT];
__device__ float g_Ay[MTOT];
__device__ float g_e1[MTOT*8];
__device__ float g_e2[MTOT*8];
__device__ float g_S [(size_t)Bn*NN*NN];      // logits / probs (134 MB)
__device__ float g_fa[(size_t)MTOT*FINx];     // feat_agg

// ---------------- f32x2 (FFMA2) helpers -------------------------------------
__device__ __forceinline__ void lds_v2u64(unsigned long long &x, unsigned long long &y,
                                          const void* p) {
    unsigned a = (unsigned)__cvta_generic_to_shared(p);
    asm volatile("ld.shared.v2.u64 {%0,%1}, [%2];" : "=l"(x), "=l"(y) : "r"(a));
}
__device__ __forceinline__ unsigned long long splat2(float b) {
    unsigned long long r;
    asm("mov.b64 %0, {%1,%1};" : "=l"(r) : "f"(b));
    return r;
}
__device__ __forceinline__ void fma2(unsigned long long &acc, unsigned long long a,
                                     unsigned long long b) {
    asm("fma.rn.f32x2 %0, %1, %2, %0;" : "+l"(acc) : "l"(a), "l"(b));
}
__device__ __forceinline__ float2 unpack2(unsigned long long v) {
    float2 f;
    asm("mov.b64 {%0,%1}, %2;" : "=f"(f.x), "=f"(f.y) : "l"(v));
    return f;
}

// ---------------- tiled SGEMM: C = A @ B (or A @ B^T) ----------------------
// BM=128, BN=64, BK=16, 128 threads. Microtile 8 rows x 8 cols per thread,
// as 4 f32x2 row-pairs x 8 cols (32 FFMA2 / 64B LDS per k: pipe-balanced).
// Double-buffered smem: one __syncthreads per k-tile.
// EPI==1: scores epilogue (+Ay[row] +Ax[col], leaky relu, adj mask).
template<bool TRANSB, int EPI>
__global__ void __launch_bounds__(128, 3)
gemm_k(const float* __restrict__ A, const float* __restrict__ Bm,
       float* __restrict__ C, int M, int N, int K,
       size_t sA, size_t sB, size_t sC,
       const float* __restrict__ Ax, const float* __restrict__ Ay,
       const int* __restrict__ adj)
{
    constexpr int BM = 128, BN = 64, BK = 16;
    __shared__ float As[2][BK][BM + 4];   // row stride 132 floats (16B aligned)
    __shared__ float Bs[2][BK][BN + 4];   // row stride 68 floats  (16B aligned)

    const int b = blockIdx.z;
    A  += (size_t)b * sA;
    Bm += (size_t)b * sB;
    C  += (size_t)b * sC;

    const int m0 = blockIdx.y * BM;
    const int n0 = blockIdx.x * BN;
    const int tid = threadIdx.x;

    // compute mapping: 16 x 8 thread grid, 8x8 microtile
    const int tx = tid & 7;           // 0..7  -> 8 cols each
    const int ty = tid >> 3;          // 0..15 -> 8 rows each

    // A loader: 4 passes of 32 rows, 4 threads per row (64B segments)
    const int arow = tid >> 2;        // 0..31
    const int acol = (tid & 3) * 4;   // 0,4,8,12
    // B loader (non-trans): 16 rows x 64 cols, 8 floats per thread
    const int brow = tid >> 3;        // 0..15
    const int bcol = (tid & 7) * 8;   // 0..56
    // B loader (trans): 64 rows(n) x 16 cols(k), 8 floats per thread along k
    const int trow = tid >> 1;        // 0..63
    const int tcol = (tid & 1) * 8;   // 0 or 8

    unsigned long long acc[4][8];
    #pragma unroll
    for (int r = 0; r < 4; r++)
        #pragma unroll
        for (int j = 0; j < 8; j++) acc[r][j] = 0ULL;

    float4 ar[4];        // A prefetch regs
    float4 br0, br1;     // B prefetch regs

    // ---- load tile 0 into regs ----
    #pragma unroll
    for (int p = 0; p < 4; p++)
        ar[p] = *(const float4*)(A + (size_t)(m0 + arow + 32 * p) * K + acol);
    if (!TRANSB) {
        br0 = *(const float4*)(Bm + (size_t)brow * N + n0 + bcol);
        br1 = *(const float4*)(Bm + (size_t)brow * N + n0 + bcol + 4);
    } else {
        br0 = *(const float4*)(Bm + (size_t)(n0 + trow) * K + tcol);
        br1 = *(const float4*)(Bm + (size_t)(n0 + trow) * K + tcol + 4);
    }

    // ---- store tile 0 to smem buf 0 ----
    #pragma unroll
    for (int p = 0; p < 4; p++) {
        As[0][acol+0][arow + 32*p] = ar[p].x;
        As[0][acol+1][arow + 32*p] = ar[p].y;
        As[0][acol+2][arow + 32*p] = ar[p].z;
        As[0][acol+3][arow + 32*p] = ar[p].w;
    }
    if (!TRANSB) {
        *(float4*)&Bs[0][brow][bcol]     = br0;
        *(float4*)&Bs[0][brow][bcol + 4] = br1;
    } else {
        Bs[0][tcol+0][trow] = br0.x; Bs[0][tcol+1][trow] = br0.y;
        Bs[0][tcol+2][trow] = br0.z; Bs[0][tcol+3][trow] = br0.w;
        Bs[0][tcol+4][trow] = br1.x; Bs[0][tcol+5][trow] = br1.y;
        Bs[0][tcol+6][trow] = br1.z; Bs[0][tcol+7][trow] = br1.w;
    }
    __syncthreads();

    int buf = 0;
    for (int k0 = 0; k0 < K; k0 += BK) {
        const int kn = k0 + BK;
        // prefetch next tile into regs (overlaps with compute)
        if (kn < K) {
            #pragma unroll
            for (int p = 0; p < 4; p++)
                ar[p] = *(const float4*)(A + (size_t)(m0 + arow + 32 * p) * K + kn + acol);
            if (!TRANSB) {
                br0 = *(const float4*)(Bm + (size_t)(kn + brow) * N + n0 + bcol);
                br1 = *(const float4*)(Bm + (size_t)(kn + brow) * N + n0 + bcol + 4);
            } else {
                br0 = *(const float4*)(Bm + (size_t)(n0 + trow) * K + kn + tcol);
                br1 = *(const float4*)(Bm + (size_t)(n0 + trow) * K + kn + tcol + 4);
            }
        }

        // ---- compute on buf ----
        #pragma unroll
        for (int k = 0; k < BK; k++) {
            unsigned long long pa0, pa1, pa2, pa3;
            lds_v2u64(pa0, pa1, &As[buf][k][ty * 8]);
            lds_v2u64(pa2, pa3, &As[buf][k][ty * 8 + 4]);
            float4 rb0 = *(const float4*)&Bs[buf][k][tx * 8];
            float4 rb1 = *(const float4*)&Bs[buf][k][tx * 8 + 4];

            unsigned long long pb;
            pb = splat2(rb0.x);
            fma2(acc[0][0], pa0, pb); fma2(acc[1][0], pa1, pb);
            fma2(acc[2][0], pa2, pb); fma2(acc[3][0], pa3, pb);
            pb = splat2(rb0.y);
            fma2(acc[0][1], pa0, pb); fma2(acc[1][1], pa1, pb);
            fma2(acc[2][1], pa2, pb); fma2(acc[3][1], pa3, pb);
            pb = splat2(rb0.z);
            fma2(acc[0][2], pa0, pb); fma2(acc[1][2], pa1, pb);
            fma2(acc[2][2], pa2, pb); fma2(acc[3][2], pa3, pb);
            pb = splat2(rb0.w);
            fma2(acc[0][3], pa0, pb); fma2(acc[1][3], pa1, pb);
            fma2(acc[2][3], pa2, pb); fma2(acc[3][3], pa3, pb);
            pb = splat2(rb1.x);
            fma2(acc[0][4], pa0, pb); fma2(acc[1][4], pa1, pb);
            fma2(acc[2][4], pa2, pb); fma2(acc[3][4], pa3, pb);
            pb = splat2(rb1.y);
            fma2(acc[0][5], pa0, pb); fma2(acc[1][5], pa1, pb);
            fma2(acc[2][5], pa2, pb); fma2(acc[3][5], pa3, pb);
            pb = splat2(rb1.z);
            fma2(acc[0][6], pa0, pb); fma2(acc[1][6], pa1, pb);
            fma2(acc[2][6], pa2, pb); fma2(acc[3][6], pa3, pb);
            pb = splat2(rb1.w);
            fma2(acc[0][7], pa0, pb); fma2(acc[1][7], pa1, pb);
            fma2(acc[2][7], pa2, pb); fma2(acc[3][7], pa3, pb);
        }

        // ---- store next tile to other buf, single sync per iter ----
        if (kn < K) {
            const int nb = buf ^ 1;
            #pragma unroll
            for (int p = 0; p < 4; p++) {
                As[nb][acol+0][arow + 32*p] = ar[p].x;
                As[nb][acol+1][arow + 32*p] = ar[p].y;
                As[nb][acol+2][arow + 32*p] = ar[p].z;
                As[nb][acol+3][arow + 32*p] = ar[p].w;
            }
            if (!TRANSB) {
                *(float4*)&Bs[nb][brow][bcol]     = br0;
                *(float4*)&Bs[nb][brow][bcol + 4] = br1;
            } else {
                Bs[nb][tcol+0][trow] = br0.x; Bs[nb][tcol+1][trow] = br0.y;
                Bs[nb][tcol+2][trow] = br0.z; Bs[nb][tcol+3][trow] = br0.w;
                Bs[nb][tcol+4][trow] = br1.x; Bs[nb][tcol+5][trow] = br1.y;
                Bs[nb][tcol+6][trow] = br1.z; Bs[nb][tcol+7][trow] = br1.w;
            }
            __syncthreads();
        }
        buf ^= 1;
    }

    // ---------------- epilogue (vectorized) ----------------
    const int nbase = n0 + tx * 8;
    #pragma unroll
    for (int r = 0; r < 4; r++) {
        float2 c[8];
        #pragma unroll
        for (int j = 0; j < 8; j++) c[j] = unpack2(acc[r][j]);
        float4 lo0 = make_float4(c[0].x, c[1].x, c[2].x, c[3].x);
        float4 lo1 = make_float4(c[4].x, c[5].x, c[6].x, c[7].x);
        float4 hi0 = make_float4(c[0].y, c[1].y, c[2].y, c[3].y);
        float4 hi1 = make_float4(c[4].y, c[5].y, c[6].y, c[7].y);
        const int m_lo = m0 + ty * 8 + 2 * r;

        if (EPI == 1) {
            float4 axv0 = *(const float4*)(Ax + b * NN + nbase);
            float4 axv1 = *(const float4*)(Ax + b * NN + nbase + 4);
            #pragma unroll
            for (int hh = 0; hh < 2; hh++) {
                const int m = m_lo + hh;
                float4 v0 = hh ? hi0 : lo0;
                float4 v1 = hh ? hi1 : lo1;
                const float ay = Ay[b * NN + m];
                v0.x += ay + axv0.x; v0.y += ay + axv0.y;
                v0.z += ay + axv0.z; v0.w += ay + axv0.w;
                v1.x += ay + axv1.x; v1.y += ay + axv1.y;
                v1.z += ay + axv1.z; v1.w += ay + axv1.w;
                v0.x = (v0.x > 0.f) ? v0.x : ALPHAc * v0.x;
                v0.y = (v0.y > 0.f) ? v0.y : ALPHAc * v0.y;
                v0.z = (v0.z > 0.f) ? v0.z : ALPHAc * v0.z;
                v0.w = (v0.w > 0.f) ? v0.w : ALPHAc * v0.w;
                v1.x = (v1.x > 0.f) ? v1.x : ALPHAc * v1.x;
                v1.y = (v1.y > 0.f) ? v1.y : ALPHAc * v1.y;
                v1.z = (v1.z > 0.f) ? v1.z : ALPHAc * v1.z;
                v1.w = (v1.w > 0.f) ? v1.w : ALPHAc * v1.w;
                const int* adp = adj + (size_t)b * NN * NN + (size_t)m * NN + nbase;
                int4 ad0 = *(const int4*)adp;
                int4 ad1 = *(const int4*)(adp + 4);
                v0.x = (ad0.x > 0) ? v0.x : NEGc;
                v0.y = (ad0.y > 0) ? v0.y : NEGc;
                v0.z = (ad0.z > 0) ? v0.z : NEGc;
                v0.w = (ad0.w > 0) ? v0.w : NEGc;
                v1.x = (ad1.x > 0) ? v1.x : NEGc;
                v1.y = (ad1.y > 0) ? v1.y : NEGc;
                v1.z = (ad1.z > 0) ? v1.z : NEGc;
                v1.w = (ad1.w > 0) ? v1.w : NEGc;
                *(float4*)(C + (size_t)m * N + nbase)     = v0;
                *(float4*)(C + (size_t)m * N + nbase + 4) = v1;
            }
        } else {
            *(float4*)(C + (size_t)m_lo       * N + nbase)     = lo0;
            *(float4*)(C + (size_t)m_lo       * N + nbase + 4) = lo1;
            *(float4*)(C + (size_t)(m_lo + 1) * N + nbase)     = hi0;
            *(float4*)(C + (size_t)(m_lo + 1) * N + nbase + 4) = hi1;
        }
    }
}

// --------- Ax = h@a1, Ay = h@a2, e1[e] = feat row . L_w[e] (warp/row) -------
__global__ void small1_k(const float* __restrict__ h, const float* __restrict__ feat,
                         const float* __restrict__ a1, const float* __restrict__ a2,
                         const float* __restrict__ Lw,
                         float* __restrict__ Ax, float* __restrict__ Ay,
                         float* __restrict__ e1)
{
    const int warp = (blockIdx.x * blockDim.x + threadIdx.x) >> 5;
    const int lane = threadIdx.x & 31;
    if (warp >= MTOT) return;

    const float* hr = h + (size_t)warp * FOUTx;
    float sx = 0.f, sy = 0.f;
    for (int k = lane; k < FOUTx; k += 32) {
        const float f = hr[k];
        sx += f * a1[k];
        sy += f * a2[k];
    }
    const float* fr = feat + (size_t)warp * FINx;
    float acc[5] = {0.f, 0.f, 0.f, 0.f, 0.f};
    for (int k = lane; k < FINx; k += 32) {
        const float f = fr[k];
        #pragma unroll
        for (int e = 0; e < 5; e++) acc[e] += f * Lw[e * FINx + k];
    }
    #pragma unroll
    for (int off = 16; off; off >>= 1) {
        sx += __shfl_xor_sync(0xffffffffu, sx, off);
        sy += __shfl_xor_sync(0xffffffffu, sy, off);
        #pragma unroll
        for (int e = 0; e < 5; e++) acc[e] += __shfl_xor_sync(0xffffffffu, acc[e], off);
    }
    if (lane == 0) {
        Ax[warp] = sx;
        Ay[warp] = sy;
        #pragma unroll
        for (int e = 0; e < 5; e++) e1[warp * 8 + e] = acc[e];
    }
}

// --------- e2[e] = feat_agg row . R_w[e] -----------------------------------
__global__ void small2_k(const float* __restrict__ fa, const float* __restrict__ Rw,
                         float* __restrict__ e2)
{
    const int warp = (blockIdx.x * blockDim.x + threadIdx.x) >> 5;
    const int lane = threadIdx.x & 31;
    if (warp >= MTOT) return;

    const float* fr = fa + (size_t)warp * FINx;
    float acc[5] = {0.f, 0.f, 0.f, 0.f, 0.f};
    for (int k = lane; k < FINx; k += 32) {
        const float f = fr[k];
        #pragma unroll
        for (int e = 0; e < 5; e++) acc[e] += f * Rw[e * FINx + k];
    }
    #pragma unroll
    for (int off = 16; off; off >>= 1) {
        #pragma unroll
        for (int e = 0; e < 5; e++) acc[e] += __shfl_xor_sync(0xffffffffu, acc[e], off);
    }
    if (lane == 0) {
        #pragma unroll
        for (int e = 0; e < 5; e++) e2[warp * 8 + e] = acc[e];
    }
}

// --------- row softmax over N=2048, in place --------------------------------
__global__ void __launch_bounds__(256)
softmax_k(float* __restrict__ S)
{
    float* p = S + (size_t)blockIdx.x * NN;
    const int t = threadIdx.x;
    float v[8];
    float mx = -3.4e38f;
    #pragma unroll
    for (int i = 0; i < 8; i++) { v[i] = p[t + i * 256]; mx = fmaxf(mx, v[i]); }

    __shared__ float red[256];
    red[t] = mx; __syncthreads();
    #pragma unroll
    for (int s = 128; s > 0; s >>= 1) {
        if (t < s) red[t] = fmaxf(red[t], red[t + s]);
        __syncthreads();
    }
    mx = red[0];
    __syncthreads();

    float sum = 0.f;
    #pragma unroll
    for (int i = 0; i < 8; i++) { v[i] = __expf(v[i] - mx); sum += v[i]; }
    red[t] = sum; __syncthreads();
    #pragma unroll
    for (int s = 128; s > 0; s >>= 1) {
        if (t < s) red[t] += red[t + s];
        __syncthreads();
    }
    const float inv = 1.0f / red[0];
    #pragma unroll
    for (int i = 0; i < 8; i++) p[t + i * 256] = v[i] * inv;
}

// --------- out = h1 + h2 + e1^T B_w[o] e2 ----------------------------------
__global__ void __launch_bounds__(256)
final_k(const float* __restrict__ h1, const float* __restrict__ h2,
        const float* __restrict__ e1, const float* __restrict__ e2,
        const float* __restrict__ Bw, float* __restrict__ out)
{
    const int m = blockIdx.x;
    const int o = threadIdx.x;   // 0..255
    __shared__ float s1[8], s2[8];
    if (o < 5) { s1[o] = e1[m * 8 + o]; s2[o] = e2[m * 8 + o]; }
    __syncthreads();

    const float* bw = Bw + o * 25;
    float s = 0.f;
    #pragma unroll
    for (int i = 0; i < 5; i++) {
        const float ei = s1[i];
        #pragma unroll
        for (int j = 0; j < 5; j++) s += ei * bw[i * 5 + j] * s2[j];
    }
    const size_t idx = (size_t)m * FOUTx + o;
    out[idx] = h1[idx] + h2[idx] + s;
}

// ---------------------------------------------------------------------------
extern "C" void kernel_launch(void* const* d_in, const int* in_sizes, int n_in,
                              void* d_out, int out_size)
{
    const float* feat = (const float*)d_in[0];
    const int*   adj  = (const int*)  d_in[1];
    const float* W    = (const float*)d_in[2];
    const float* W1   = (const float*)d_in[3];
    const float* W2   = (const float*)d_in[4];
    const float* a1   = (const float*)d_in[5];
    const float* a2   = (const float*)d_in[6];
    const float* a12  = (const float*)d_in[7];
    const float* Lw   = (const float*)d_in[8];
    const float* Rw   = (const float*)d_in[9];
    const float* Bw   = (const float*)d_in[10];
    float* out = (float*)d_out;

    float *h, *h1, *g, *h2, *Ax, *Ay, *e1, *e2, *S, *fa;
    cudaGetSymbolAddress((void**)&h,  g_h);
    cudaGetSymbolAddress((void**)&h1, g_h1);
    cudaGetSymbolAddress((void**)&g,  g_g);
    cudaGetSymbolAddress((void**)&h2, g_h2);
    cudaGetSymbolAddress((void**)&Ax, g_Ax);
    cudaGetSymbolAddress((void**)&Ay, g_Ay);
    cudaGetSymbolAddress((void**)&e1, g_e1);
    cudaGetSymbolAddress((void**)&e2, g_e2);
    cudaGetSymbolAddress((void**)&S,  g_S);
    cudaGetSymbolAddress((void**)&fa, g_fa);

    const dim3 blk(128);

    // h = feat @ W ; h1 = feat @ W1
    gemm_k<false,0><<<dim3(FOUTx/64, MTOT/128, 1), blk>>>(
        feat, W,  h,  MTOT, FOUTx, FINx, 0, 0, 0, nullptr, nullptr, nullptr);
    gemm_k<false,0><<<dim3(FOUTx/64, MTOT/128, 1), blk>>>(
        feat, W1, h1, MTOT, FOUTx, FINx, 0, 0, 0, nullptr, nullptr, nullptr);

    // Ax, Ay, e1
    small1_k<<<MTOT/8, 256>>>(h, feat, a1, a2, Lw, Ax, Ay, e1);

    // g = h @ a12
    gemm_k<false,0><<<dim3(FOUTx/64, MTOT/128, 1), blk>>>(
        h, a12, g, MTOT, FOUTx, FOUTx, 0, 0, 0, nullptr, nullptr, nullptr);

    // S[b,i,j] = leaky(Ax[j]+Ay[i]+g_i.h_j) masked by adj  (batched NT GEMM)
    gemm_k<true,1><<<dim3(NN/64, NN/128, Bn), blk>>>(
        g, h, S, NN, NN, FOUTx,
        (size_t)NN*FOUTx, (size_t)NN*FOUTx, (size_t)NN*NN, Ax, Ay, adj);

    // row softmax (in place)
    softmax_k<<<MTOT, 256>>>(S);

    // feat_agg = P @ feat  (batched NN GEMM)
    gemm_k<false,0><<<dim3(FINx/64, NN/128, Bn), blk>>>(
        S, feat, fa, NN, FINx, NN,
        (size_t)NN*NN, (size_t)NN*FINx, (size_t)NN*FINx, nullptr, nullptr, nullptr);

    // e2
    small2_k<<<MTOT/8, 256>>>(fa, Rw, e2);

    // h2 = feat_agg @ W2
    gemm_k<false,0><<<dim3(FOUTx/64, MTOT/128, 1), blk>>>(
        fa, W2, h2, MTOT, FOUTx, FINx, 0, 0, 0, nullptr, nullptr, nullptr);

    // out = h1 + h2 + bilinear(e1, B_w, e2)
    final_k<<<MTOT, 256>>>(h1, h2, e1, e2, Bw, out);
}

// round 10
// speedup vs baseline: 1.4276x; 1.4276x over previous
#include <cuda_runtime.h>
#include <cuda_bf16.h>
#include <cstdint>

// Problem constants
#define Bn    8
#define NN    2048
#define FINx  512
#define FOUTx 256
#define MTOT  (Bn*NN)          // 16384
#define ALPHAc 0.2f
#define NEGc  (-9e15f)

// ---------------- scratch (device globals: allocation-free) ----------------
__device__ float g_h [MTOT*FOUTx];            // feat@W
__device__ float g_h1[MTOT*FOUTx];            // feat@W1
__device__ float g_g [MTOT*FOUTx];            // h@a12
__device__ float g_h2[MTOT*FOUTx];            // fa@W2
__device__ float g_Ax[MTOT];
__device__ float g_Ay[MTOT];
__device__ float g_e1[MTOT*8];
__device__ float g_e2[MTOT*8];
__device__ float g_S [(size_t)Bn*NN*NN];      // logits (134 MB)
__device__ __nv_bfloat16 g_Shi[(size_t)Bn*NN*NN];   // probs hi (67 MB)
__device__ __nv_bfloat16 g_Slo[(size_t)Bn*NN*NN];   // probs lo (67 MB)
__device__ __nv_bfloat16 g_Fhi[(size_t)Bn*FINx*NN]; // featT hi (16 MB)
__device__ __nv_bfloat16 g_Flo[(size_t)Bn*FINx*NN]; // featT lo (16 MB)
__device__ float g_fa[(size_t)MTOT*FINx];     // feat_agg

// ---------------- f32x2 (FFMA2) helpers -------------------------------------
__device__ __forceinline__ void lds_v2u64(unsigned long long &x, unsigned long long &y,
                                          const void* p) {
    unsigned a = (unsigned)__cvta_generic_to_shared(p);
    asm volatile("ld.shared.v2.u64 {%0,%1}, [%2];" : "=l"(x), "=l"(y) : "r"(a));
}
__device__ __forceinline__ unsigned long long splat2(float b) {
    unsigned long long r;
    asm("mov.b64 %0, {%1,%1};" : "=l"(r) : "f"(b));
    return r;
}
__device__ __forceinline__ void fma2(unsigned long long &acc, unsigned long long a,
                                     unsigned long long b) {
    asm("fma.rn.f32x2 %0, %1, %2, %0;" : "+l"(acc) : "l"(a), "l"(b));
}
__device__ __forceinline__ float2 unpack2(unsigned long long v) {
    float2 f;
    asm("mov.b64 {%0,%1}, %2;" : "=f"(f.x), "=f"(f.y) : "l"(v));
    return f;
}

// ---------------- mma.sync / cp.async helpers (sm_80+; no 'a' features) ----
__device__ __forceinline__ uint32_t smem_u32(const void* p) {
    return (uint32_t)__cvta_generic_to_shared(p);
}
__device__ __forceinline__ void cp16(uint32_t s, const void* g) {
    asm volatile("cp.async.cg.shared.global [%0], [%1], 16;" :: "r"(s), "l"(g));
}
__device__ __forceinline__ void ldmx4(uint32_t* d, uint32_t a) {
    asm volatile("ldmatrix.sync.aligned.m8n8.x4.shared.b16 {%0,%1,%2,%3}, [%4];"
                 : "=r"(d[0]), "=r"(d[1]), "=r"(d[2]), "=r"(d[3]) : "r"(a));
}
__device__ __forceinline__ void mma_bf16(float* c, const uint32_t* a,
                                         uint32_t b0, uint32_t b1) {
    asm volatile("mma.sync.aligned.m16n8k16.row.col.f32.bf16.bf16.f32 "
                 "{%0,%1,%2,%3}, {%4,%5,%6,%7}, {%8,%9}, {%0,%1,%2,%3};"
                 : "+f"(c[0]), "+f"(c[1]), "+f"(c[2]), "+f"(c[3])
                 : "r"(a[0]), "r"(a[1]), "r"(a[2]), "r"(a[3]), "r"(b0), "r"(b1));
}

// ---------------- tiled SGEMM (R7 winner): C = A @ B (or A @ B^T) ----------
template<bool TRANSB, int EPI>
__global__ void __launch_bounds__(256)
gemm_k(const float* __restrict__ A, const float* __restrict__ Bm,
       float* __restrict__ C, int M, int N, int K,
       size_t sA, size_t sB, size_t sC,
       const float* __restrict__ Ax, const float* __restrict__ Ay,
       const int* __restrict__ adj)
{
    constexpr int BM = 128, BN = 64, BK = 16;
    __shared__ float As[BK][BM + 4];
    __shared__ float Bs[BK][BN + 4];

    const int b = blockIdx.z;
    A  += (size_t)b * sA;
    Bm += (size_t)b * sB;
    C  += (size_t)b * sC;

    const int m0 = blockIdx.y * BM;
    const int n0 = blockIdx.x * BN;
    const int tid = threadIdx.x;
    const int tx = tid & 15;
    const int ty = tid >> 4;
    const int arow = tid >> 2;
    const int acol = (tid & 3) * 4;
    const int brow = tid >> 4;
    const int bcol = (tid & 15) * 4;

    unsigned long long acc[4][4];
    #pragma unroll
    for (int r = 0; r < 4; r++)
        #pragma unroll
        for (int j = 0; j < 4; j++) acc[r][j] = 0ULL;

    float4 a0, a1v, bv;
    a0  = *(const float4*)(A + (size_t)(m0 + arow)      * K + acol);
    a1v = *(const float4*)(A + (size_t)(m0 + arow + 64) * K + acol);
    if (!TRANSB) bv = *(const float4*)(Bm + (size_t)brow * N + n0 + bcol);
    else         bv = *(const float4*)(Bm + (size_t)(n0 + arow) * K + acol);

    for (int k0 = 0; k0 < K; k0 += BK) {
        As[acol+0][arow]    = a0.x;  As[acol+1][arow]    = a0.y;
        As[acol+2][arow]    = a0.z;  As[acol+3][arow]    = a0.w;
        As[acol+0][arow+64] = a1v.x; As[acol+1][arow+64] = a1v.y;
        As[acol+2][arow+64] = a1v.z; As[acol+3][arow+64] = a1v.w;
        if (!TRANSB) {
            Bs[brow][bcol+0] = bv.x; Bs[brow][bcol+1] = bv.y;
            Bs[brow][bcol+2] = bv.z; Bs[brow][bcol+3] = bv.w;
        } else {
            Bs[acol+0][arow] = bv.x; Bs[acol+1][arow] = bv.y;
            Bs[acol+2][arow] = bv.z; Bs[acol+3][arow] = bv.w;
        }
        __syncthreads();

        const int kn = k0 + BK;
        if (kn < K) {
            a0  = *(const float4*)(A + (size_t)(m0 + arow)      * K + kn + acol);
            a1v = *(const float4*)(A + (size_t)(m0 + arow + 64) * K + kn + acol);
            if (!TRANSB) bv = *(const float4*)(Bm + (size_t)(kn + brow) * N + n0 + bcol);
            else         bv = *(const float4*)(Bm + (size_t)(n0 + arow) * K + kn + acol);
        }

        #pragma unroll
        for (int k = 0; k < BK; k++) {
            unsigned long long pa0, pa1, pa2, pa3;
            lds_v2u64(pa0, pa1, &As[k][ty * 8]);
            lds_v2u64(pa2, pa3, &As[k][ty * 8 + 4]);
            float4 rb = *(const float4*)&Bs[k][tx * 4];
            unsigned long long pb0 = splat2(rb.x), pb1 = splat2(rb.y);
            unsigned long long pb2 = splat2(rb.z), pb3 = splat2(rb.w);

            fma2(acc[0][0], pa0, pb0); fma2(acc[0][1], pa0, pb1);
            fma2(acc[0][2], pa0, pb2); fma2(acc[0][3], pa0, pb3);
            fma2(acc[1][0], pa1, pb0); fma2(acc[1][1], pa1, pb1);
            fma2(acc[1][2], pa1, pb2); fma2(acc[1][3], pa1, pb3);
            fma2(acc[2][0], pa2, pb0); fma2(acc[2][1], pa2, pb1);
            fma2(acc[2][2], pa2, pb2); fma2(acc[2][3], pa2, pb3);
            fma2(acc[3][0], pa3, pb0); fma2(acc[3][1], pa3, pb1);
            fma2(acc[3][2], pa3, pb2); fma2(acc[3][3], pa3, pb3);
        }
        __syncthreads();
    }

    const int nbase = n0 + tx * 4;
    #pragma unroll
    for (int r = 0; r < 4; r++) {
        float2 c0 = unpack2(acc[r][0]);
        float2 c1 = unpack2(acc[r][1]);
        float2 c2 = unpack2(acc[r][2]);
        float2 c3 = unpack2(acc[r][3]);
        float4 row_lo = make_float4(c0.x, c1.x, c2.x, c3.x);
        float4 row_hi = make_float4(c0.y, c1.y, c2.y, c3.y);
        const int m_lo = m0 + ty * 8 + 2 * r;

        if (EPI == 1) {
            const float ax0 = Ax[b * NN + nbase + 0];
            const float ax1 = Ax[b * NN + nbase + 1];
            const float ax2 = Ax[b * NN + nbase + 2];
            const float ax3 = Ax[b * NN + nbase + 3];
            #pragma unroll
            for (int hh = 0; hh < 2; hh++) {
                const int m = m_lo + hh;
                float4 v = hh ? row_hi : row_lo;
                const float ay = Ay[b * NN + m];
                v.x += ay + ax0; v.y += ay + ax1; v.z += ay + ax2; v.w += ay + ax3;
                v.x = (v.x > 0.f) ? v.x : ALPHAc * v.x;
                v.y = (v.y > 0.f) ? v.y : ALPHAc * v.y;
                v.z = (v.z > 0.f) ? v.z : ALPHAc * v.z;
                v.w = (v.w > 0.f) ? v.w : ALPHAc * v.w;
                int4 ad = *(const int4*)(adj + (size_t)b * NN * NN + (size_t)m * NN + nbase);
                v.x = (ad.x > 0) ? v.x : NEGc;
                v.y = (ad.y > 0) ? v.y : NEGc;
                v.z = (ad.z > 0) ? v.z : NEGc;
                v.w = (ad.w > 0) ? v.w : NEGc;
                *(float4*)(C + (size_t)m * N + nbase) = v;
            }
        } else {
            *(float4*)(C + (size_t)m_lo       * N + nbase) = row_lo;
            *(float4*)(C + (size_t)(m_lo + 1) * N + nbase) = row_hi;
        }
    }
}

// ---------------- HMMA agg GEMM: fa = P @ feat (bf16 3-pass split) ---------
// CTA tile 128(M) x 128(N), 256 threads = 8 warps (4m x 2n), warp tile 32x64.
// A = probs [M,K] row-major (hi/lo), B = featT [N,K] K-contig (hi/lo).
// K chunks of 32, cp.async double-buffered smem, 80B smem rows (conflict-free).
#define AGG_ROWB  80                   // smem row stride in bytes (40 bf16)
#define AGG_ARR   10240                // one 128x40-bf16 array
#define AGG_BUF   (4*AGG_ARR)          // Ah,Al,Bh,Bl
#define AGG_SMEM  (2*AGG_BUF)          // double buffer = 80 KB

__global__ void __launch_bounds__(256)
agg_mma_k(const __nv_bfloat16* __restrict__ Shi, const __nv_bfloat16* __restrict__ Slo,
          const __nv_bfloat16* __restrict__ Fhi, const __nv_bfloat16* __restrict__ Flo,
          float* __restrict__ fa)
{
    extern __shared__ char smem[];
    const uint32_t sbase = smem_u32(smem);
    const int tid  = threadIdx.x;
    const int wid  = tid >> 5;
    const int lane = tid & 31;
    const int b  = blockIdx.z;
    const int m0 = blockIdx.y * 128;
    const int n0 = blockIdx.x * 128;

    // loader mapping: 64 rows x 4 segs; each thread rows {r, r+64}, 16B per row
    const int r   = tid >> 2;
    const int seg = tid & 3;
    const __nv_bfloat16* gAh = Shi + ((size_t)(b * NN  + m0 + r)) * NN + seg * 8;
    const __nv_bfloat16* gAl = Slo + ((size_t)(b * NN  + m0 + r)) * NN + seg * 8;
    const __nv_bfloat16* gBh = Fhi + ((size_t)(b * FINx + n0 + r)) * NN + seg * 8;
    const __nv_bfloat16* gBl = Flo + ((size_t)(b * FINx + n0 + r)) * NN + seg * 8;
    const uint32_t sA = r * AGG_ROWB + seg * 16;
    const size_t  gstep = (size_t)64 * NN;

    #define AGG_ISSUE(bufi, kc) do {                                           \
        const int kofs = (kc) * 32;                                            \
        uint32_t s0 = sbase + (bufi) * AGG_BUF + sA;                            \
        cp16(s0 + 0*AGG_ARR,               gAh + kofs);                         \
        cp16(s0 + 1*AGG_ARR,               gAl + kofs);                         \
        cp16(s0 + 2*AGG_ARR,               gBh + kofs);                         \
        cp16(s0 + 3*AGG_ARR,               gBl + kofs);                         \
        uint32_t s1 = s0 + 64 * AGG_ROWB;                                       \
        cp16(s1 + 0*AGG_ARR,               gAh + gstep + kofs);                 \
        cp16(s1 + 1*AGG_ARR,               gAl + gstep + kofs);                 \
        cp16(s1 + 2*AGG_ARR,               gBh + gstep + kofs);                 \
        cp16(s1 + 3*AGG_ARR,               gBl + gstep + kofs);                 \
        asm volatile("cp.async.commit_group;" ::: "memory");                    \
    } while (0)

    // warp tiling
    const int wm = wid & 3;    // 4 m-warps: rows wm*32..+32
    const int wn = wid >> 2;   // 2 n-warps: cols wn*64..+64

    float acc[2][8][4];
    #pragma unroll
    for (int mi = 0; mi < 2; mi++)
        #pragma unroll
        for (int nj = 0; nj < 8; nj++)
            #pragma unroll
            for (int q = 0; q < 4; q++) acc[mi][nj][q] = 0.f;

    AGG_ISSUE(0, 0);
    int buf = 0;
    for (int kc = 0; kc < NN / 32; kc++) {
        if (kc + 1 < NN / 32) {
            AGG_ISSUE(buf ^ 1, kc + 1);
            asm volatile("cp.async.wait_group 1;" ::: "memory");
        } else {
            asm volatile("cp.async.wait_group 0;" ::: "memory");
        }
        __syncthreads();

        const uint32_t base = sbase + buf * AGG_BUF;
        #pragma unroll
        for (int kq = 0; kq < 2; kq++) {
            // A frags (both hi and lo, both m16 tiles)
            const uint32_t aaddr = base
                + (uint32_t)((wm * 32 + (lane & 15)) * AGG_ROWB)
                + (uint32_t)((kq * 16 + (lane >> 4) * 8) * 2);
            uint32_t ah0[4], ah1[4], al0[4], al1[4];
            ldmx4(ah0, aaddr);
            ldmx4(ah1, aaddr + 16 * AGG_ROWB);
            ldmx4(al0, aaddr + 1*AGG_ARR);
            ldmx4(al1, aaddr + 1*AGG_ARR + 16 * AGG_ROWB);

            #pragma unroll
            for (int np = 0; np < 4; np++) {
                const uint32_t baddr = base + 2*AGG_ARR
                    + (uint32_t)((wn * 64 + np * 16 + (lane & 7) + ((lane >> 4) << 3)) * AGG_ROWB)
                    + (uint32_t)((kq * 16 + ((lane >> 3) & 1) * 8) * 2);
                uint32_t bh[4], bl[4];
                ldmx4(bh, baddr);
                ldmx4(bl, baddr + 1*AGG_ARR);
                const int j0 = np * 2, j1 = np * 2 + 1;
                // pass 1: Ah*Bh
                mma_bf16(acc[0][j0], ah0, bh[0], bh[1]);
                mma_bf16(acc[0][j1], ah0, bh[2], bh[3]);
                mma_bf16(acc[1][j0], ah1, bh[0], bh[1]);
                mma_bf16(acc[1][j1], ah1, bh[2], bh[3]);
                // pass 2: Ah*Bl
                mma_bf16(acc[0][j0], ah0, bl[0], bl[1]);
                mma_bf16(acc[0][j1], ah0, bl[2], bl[3]);
                mma_bf16(acc[1][j0], ah1, bl[0], bl[1]);
                mma_bf16(acc[1][j1], ah1, bl[2], bl[3]);
                // pass 3: Al*Bh
                mma_bf16(acc[0][j0], al0, bh[0], bh[1]);
                mma_bf16(acc[0][j1], al0, bh[2], bh[3]);
                mma_bf16(acc[1][j0], al1, bh[0], bh[1]);
                mma_bf16(acc[1][j1], al1, bh[2], bh[3]);
            }
        }
        __syncthreads();
        buf ^= 1;
    }
    #undef AGG_ISSUE

    // epilogue: write fp32 fa
    const int mbase = m0 + wm * 32;
    const int nbase = n0 + wn * 64;
    #pragma unroll
    for (int mi = 0; mi < 2; mi++) {
        #pragma unroll
        for (int nj = 0; nj < 8; nj++) {
            const int mm = mbase + mi * 16 + (lane >> 2);
            const int nc = nbase + nj * 8 + (lane & 3) * 2;
            float* d0 = fa + ((size_t)(b * NN) + mm) * FINx + nc;
            *(float2*)d0                 = make_float2(acc[mi][nj][0], acc[mi][nj][1]);
            *(float2*)(d0 + 8 * FINx)    = make_float2(acc[mi][nj][2], acc[mi][nj][3]);
        }
    }
}

// --------- transpose + bf16 split: featT_hi/lo[b][f][n] = split(feat[b][n][f])
__global__ void transpose_split_k(const float* __restrict__ feat,
                                  __nv_bfloat16* __restrict__ Fhi,
                                  __nv_bfloat16* __restrict__ Flo)
{
    __shared__ float t[32][33];
    const int b  = blockIdx.z;
    const int n0 = blockIdx.x * 32;
    const int f0 = blockIdx.y * 32;
    const int tx = threadIdx.x, ty = threadIdx.y;   // (32, 8)

    #pragma unroll
    for (int i = 0; i < 4; i++)
        t[ty + 8*i][tx] = feat[((size_t)b * NN + n0 + ty + 8*i) * FINx + f0 + tx];
    __syncthreads();
    #pragma unroll
    for (int i = 0; i < 4; i++) {
        const float v = t[tx][ty + 8*i];
        const __nv_bfloat16 hi = __float2bfloat16_rn(v);
        const __nv_bfloat16 lo = __float2bfloat16_rn(v - __bfloat162float(hi));
        const size_t idx = ((size_t)b * FINx + f0 + ty + 8*i) * NN + n0 + tx;
        Fhi[idx] = hi;
        Flo[idx] = lo;
    }
}

// --------- Ax = h@a1, Ay = h@a2, e1[e] = feat row . L_w[e] (warp/row) -------
__global__ void small1_k(const float* __restrict__ h, const float* __restrict__ feat,
                         const float* __restrict__ a1, const float* __restrict__ a2,
                         const float* __restrict__ Lw,
                         float* __restrict__ Ax, float* __restrict__ Ay,
                         float* __restrict__ e1)
{
    const int warp = (blockIdx.x * blockDim.x + threadIdx.x) >> 5;
    const int lane = threadIdx.x & 31;
    if (warp >= MTOT) return;

    const float* hr = h + (size_t)warp * FOUTx;
    float sx = 0.f, sy = 0.f;
    for (int k = lane; k < FOUTx; k += 32) {
        const float f = hr[k];
        sx += f * a1[k];
        sy += f * a2[k];
    }
    const float* fr = feat + (size_t)warp * FINx;
    float acc[5] = {0.f, 0.f, 0.f, 0.f, 0.f};
    for (int k = lane; k < FINx; k += 32) {
        const float f = fr[k];
        #pragma unroll
        for (int e = 0; e < 5; e++) acc[e] += f * Lw[e * FINx + k];
    }
    #pragma unroll
    for (int off = 16; off; off >>= 1) {
        sx += __shfl_xor_sync(0xffffffffu, sx, off);
        sy += __shfl_xor_sync(0xffffffffu, sy, off);
        #pragma unroll
        for (int e = 0; e < 5; e++) acc[e] += __shfl_xor_sync(0xffffffffu, acc[e], off);
    }
    if (lane == 0) {
        Ax[warp] = sx;
        Ay[warp] = sy;
        #pragma unroll
        for (int e = 0; e < 5; e++) e1[warp * 8 + e] = acc[e];
    }
}

// --------- e2[e] = feat_agg row . R_w[e] -----------------------------------
__global__ void small2_k(const float* __restrict__ fa, const float* __restrict__ Rw,
                         float* __restrict__ e2)
{
    const int warp = (blockIdx.x * blockDim.x + threadIdx.x) >> 5;
    const int lane = threadIdx.x & 31;
    if (warp >= MTOT) return;

    const float* fr = fa + (size_t)warp * FINx;
    float acc[5] = {0.f, 0.f, 0.f, 0.f, 0.f};
    for (int k = lane; k < FINx; k += 32) {
        const float f = fr[k];
        #pragma unroll
        for (int e = 0; e < 5; e++) acc[e] += f * Rw[e * FINx + k];
    }
    #pragma unroll
    for (int off = 16; off; off >>= 1) {
        #pragma unroll
        for (int e = 0; e < 5; e++) acc[e] += __shfl_xor_sync(0xffffffffu, acc[e], off);
    }
    if (lane == 0) {
        #pragma unroll
        for (int e = 0; e < 5; e++) e2[warp * 8 + e] = acc[e];
    }
}

// --------- row softmax over N=2048 -> bf16 hi/lo probs ----------------------
__global__ void __launch_bounds__(256)
softmax_k(const float* __restrict__ S,
          __nv_bfloat16* __restrict__ Phi, __nv_bfloat16* __restrict__ Plo)
{
    const float* p = S + (size_t)blockIdx.x * NN;
    const int t = threadIdx.x;
    float v[8];
    float mx = -3.4e38f;
    #pragma unroll
    for (int i = 0; i < 8; i++) { v[i] = p[t + i * 256]; mx = fmaxf(mx, v[i]); }

    __shared__ float red[256];
    red[t] = mx; __syncthreads();
    #pragma unroll
    for (int s = 128; s > 0; s >>= 1) {
        if (t < s) red[t] = fmaxf(red[t], red[t + s]);
        __syncthreads();
    }
    mx = red[0];
    __syncthreads();

    float sum = 0.f;
    #pragma unroll
    for (int i = 0; i < 8; i++) { v[i] = __expf(v[i] - mx); sum += v[i]; }
    red[t] = sum; __syncthreads();
    #pragma unroll
    for (int s = 128; s > 0; s >>= 1) {
        if (t < s) red[t] += red[t + s];
        __syncthreads();
    }
    const float inv = 1.0f / red[0];
    __nv_bfloat16* ph = Phi + (size_t)blockIdx.x * NN;
    __nv_bfloat16* pl = Plo + (size_t)blockIdx.x * NN;
    #pragma unroll
    for (int i = 0; i < 8; i++) {
        const float pv = v[i] * inv;
        const __nv_bfloat16 hi = __float2bfloat16_rn(pv);
        const __nv_bfloat16 lo = __float2bfloat16_rn(pv - __bfloat162float(hi));
        ph[t + i * 256] = hi;
        pl[t + i * 256] = lo;
    }
}

// --------- out = h1 + h2 + e1^T B_w[o] e2 ----------------------------------
__global__ void __launch_bounds__(256)
final_k(const float* __restrict__ h1, const float* __restrict__ h2,
        const float* __restrict__ e1, const float* __restrict__ e2,
        const float* __restrict__ Bw, float* __restrict__ out)
{
    const int m = blockIdx.x;
    const int o = threadIdx.x;   // 0..255
    __shared__ float s1[8], s2[8];
    if (o < 5) { s1[o] = e1[m * 8 + o]; s2[o] = e2[m * 8 + o]; }
    __syncthreads();

    const float* bw = Bw + o * 25;
    float s = 0.f;
    #pragma unroll
    for (int i = 0; i < 5; i++) {
        const float ei = s1[i];
        #pragma unroll
        for (int j = 0; j < 5; j++) s += ei * bw[i * 5 + j] * s2[j];
    }
    const size_t idx = (size_t)m * FOUTx + o;
    out[idx] = h1[idx] + h2[idx] + s;
}

// ---------------------------------------------------------------------------
extern "C" void kernel_launch(void* const* d_in, const int* in_sizes, int n_in,
                              void* d_out, int out_size)
{
    const float* feat = (const float*)d_in[0];
    const int*   adj  = (const int*)  d_in[1];
    const float* W    = (const float*)d_in[2];
    const float* W1   = (const float*)d_in[3];
    const float* W2   = (const float*)d_in[4];
    const float* a1   = (const float*)d_in[5];
    const float* a2   = (const float*)d_in[6];
    const float* a12  = (const float*)d_in[7];
    const float* Lw   = (const float*)d_in[8];
    const float* Rw   = (const float*)d_in[9];
    const float* Bw   = (const float*)d_in[10];
    float* out = (float*)d_out;

    float *h, *h1, *g, *h2, *Ax, *Ay, *e1, *e2, *S, *fa;
    __nv_bfloat16 *Shi, *Slo, *Fhi, *Flo;
    cudaGetSymbolAddress((void**)&h,  g_h);
    cudaGetSymbolAddress((void**)&h1, g_h1);
    cudaGetSymbolAddress((void**)&g,  g_g);
    cudaGetSymbolAddress((void**)&h2, g_h2);
    cudaGetSymbolAddress((void**)&Ax, g_Ax);
    cudaGetSymbolAddress((void**)&Ay, g_Ay);
    cudaGetSymbolAddress((void**)&e1, g_e1);
    cudaGetSymbolAddress((void**)&e2, g_e2);
    cudaGetSymbolAddress((void**)&S,  g_S);
    cudaGetSymbolAddress((void**)&fa, g_fa);
    cudaGetSymbolAddress((void**)&Shi, g_Shi);
    cudaGetSymbolAddress((void**)&Slo, g_Slo);
    cudaGetSymbolAddress((void**)&Fhi, g_Fhi);
    cudaGetSymbolAddress((void**)&Flo, g_Flo);

    static int smem_set = 0;
    if (!smem_set) {
        cudaFuncSetAttribute(agg_mma_k, cudaFuncAttributeMaxDynamicSharedMemorySize,
                             AGG_SMEM);
        smem_set = 1;
    }

    const dim3 blk(256);

    // featT hi/lo split (independent of everything else)
    transpose_split_k<<<dim3(NN/32, FINx/32, Bn), dim3(32, 8)>>>(feat, Fhi, Flo);

    // h = feat @ W ; h1 = feat @ W1
    gemm_k<false,0><<<dim3(FOUTx/64, MTOT/128, 1), blk>>>(
        feat, W,  h,  MTOT, FOUTx, FINx, 0, 0, 0, nullptr, nullptr, nullptr);
    gemm_k<false,0><<<dim3(FOUTx/64, MTOT/128, 1), blk>>>(
        feat, W1, h1, MTOT, FOUTx, FINx, 0, 0, 0, nullptr, nullptr, nullptr);

    // Ax, Ay, e1
    small1_k<<<MTOT/8, 256>>>(h, feat, a1, a2, Lw, Ax, Ay, e1);

    // g = h @ a12
    gemm_k<false,0><<<dim3(FOUTx/64, MTOT/128, 1), blk>>>(
        h, a12, g, MTOT, FOUTx, FOUTx, 0, 0, 0, nullptr, nullptr, nullptr);

    // S[b,i,j] = leaky(Ax[j]+Ay[i]+g_i.h_j) masked by adj  (batched NT GEMM)
    gemm_k<true,1><<<dim3(NN/64, NN/128, Bn), blk>>>(
        g, h, S, NN, NN, FOUTx,
        (size_t)NN*FOUTx, (size_t)NN*FOUTx, (size_t)NN*NN, Ax, Ay, adj);

    // row softmax -> bf16 hi/lo probs
    softmax_k<<<MTOT, 256>>>(S, Shi, Slo);

    // feat_agg = P @ feat  (HMMA mma.sync, bf16 split x3)
    agg_mma_k<<<dim3(FINx/128, NN/128, Bn), blk, AGG_SMEM>>>(Shi, Slo, Fhi, Flo, fa);

    // e2
    small2_k<<<MTOT/8, 256>>>(fa, Rw, e2);

    // h2 = feat_agg @ W2
    gemm_k<false,0><<<dim3(FOUTx/64, MTOT/128, 1), blk>>>(
        fa, W2, h2, MTOT, FOUTx, FINx, 0, 0, 0, nullptr, nullptr, nullptr);

    // out = h1 + h2 + bilinear(e1, B_w, e2)
    final_k<<<MTOT, 256>>>(h1, h2, e1, e2, Bw, out);
}

// round 11
// speedup vs baseline: 1.5754x; 1.1035x over previous
#include <cuda_runtime.h>
#include <cuda_bf16.h>
#include <cstdint>

// Problem constants
#define Bn    8
#define NN    2048
#define FINx  512
#define FOUTx 256
#define MTOT  (Bn*NN)          // 16384
#define ALPHAc 0.2f
#define NEGc  (-9e15f)

// ---------------- scratch (device globals: allocation-free) ----------------
__device__ float g_h [MTOT*FOUTx];            // feat@W
__device__ float g_h1[MTOT*FOUTx];            // feat@W1
__device__ float g_g [MTOT*FOUTx];            // h@a12
__device__ float g_h2[MTOT*FOUTx];            // fa@W2
__device__ float g_Ax[MTOT];
__device__ float g_Ay[MTOT];
__device__ float g_e1[MTOT*8];
__device__ float g_e2[MTOT*8];
__device__ float g_S [(size_t)Bn*NN*NN];      // logits (134 MB)
__device__ __nv_bfloat16 g_Shi[(size_t)Bn*NN*NN];   // probs hi (67 MB)
__device__ __nv_bfloat16 g_Slo[(size_t)Bn*NN*NN];   // probs lo (67 MB)
__device__ __nv_bfloat16 g_Fhi[(size_t)Bn*FINx*NN]; // featT hi (16 MB)
__device__ __nv_bfloat16 g_Flo[(size_t)Bn*FINx*NN]; // featT lo (16 MB)
__device__ __nv_bfloat16 g_ghi[MTOT*FOUTx];   // g hi (8 MB)
__device__ __nv_bfloat16 g_glo[MTOT*FOUTx];   // g lo
__device__ __nv_bfloat16 g_hhi[MTOT*FOUTx];   // h hi
__device__ __nv_bfloat16 g_hlo[MTOT*FOUTx];   // h lo
__device__ float g_fa[(size_t)MTOT*FINx];     // feat_agg

// ---------------- f32x2 (FFMA2) helpers -------------------------------------
__device__ __forceinline__ void lds_v2u64(unsigned long long &x, unsigned long long &y,
                                          const void* p) {
    unsigned a = (unsigned)__cvta_generic_to_shared(p);
    asm volatile("ld.shared.v2.u64 {%0,%1}, [%2];" : "=l"(x), "=l"(y) : "r"(a));
}
__device__ __forceinline__ unsigned long long splat2(float b) {
    unsigned long long r;
    asm("mov.b64 %0, {%1,%1};" : "=l"(r) : "f"(b));
    return r;
}
__device__ __forceinline__ void fma2(unsigned long long &acc, unsigned long long a,
                                     unsigned long long b) {
    asm("fma.rn.f32x2 %0, %1, %2, %0;" : "+l"(acc) : "l"(a), "l"(b));
}
__device__ __forceinline__ float2 unpack2(unsigned long long v) {
    float2 f;
    asm("mov.b64 {%0,%1}, %2;" : "=f"(f.x), "=f"(f.y) : "l"(v));
    return f;
}

// ---------------- mma.sync / cp.async helpers (sm_80+) ----------------------
__device__ __forceinline__ uint32_t smem_u32(const void* p) {
    return (uint32_t)__cvta_generic_to_shared(p);
}
__device__ __forceinline__ void cp16(uint32_t s, const void* g) {
    asm volatile("cp.async.cg.shared.global [%0], [%1], 16;" :: "r"(s), "l"(g));
}
__device__ __forceinline__ void ldmx4(uint32_t* d, uint32_t a) {
    asm volatile("ldmatrix.sync.aligned.m8n8.x4.shared.b16 {%0,%1,%2,%3}, [%4];"
                 : "=r"(d[0]), "=r"(d[1]), "=r"(d[2]), "=r"(d[3]) : "r"(a));
}
__device__ __forceinline__ void mma_bf16(float* c, const uint32_t* a,
                                         uint32_t b0, uint32_t b1) {
    asm volatile("mma.sync.aligned.m16n8k16.row.col.f32.bf16.bf16.f32 "
                 "{%0,%1,%2,%3}, {%4,%5,%6,%7}, {%8,%9}, {%0,%1,%2,%3};"
                 : "+f"(c[0]), "+f"(c[1]), "+f"(c[2]), "+f"(c[3])
                 : "r"(a[0]), "r"(a[1]), "r"(a[2]), "r"(a[3]), "r"(b0), "r"(b1));
}
__device__ __forceinline__ float lrelu(float v) {
    return (v > 0.f) ? v : ALPHAc * v;
}

// ---------------- tiled SGEMM (R7 winner): C = A @ B ------------------------
template<bool TRANSB, int EPI>
__global__ void __launch_bounds__(256)
gemm_k(const float* __restrict__ A, const float* __restrict__ Bm,
       float* __restrict__ C, int M, int N, int K,
       size_t sA, size_t sB, size_t sC,
       const float* __restrict__ Ax, const float* __restrict__ Ay,
       const int* __restrict__ adj)
{
    constexpr int BM = 128, BN = 64, BK = 16;
    __shared__ float As[BK][BM + 4];
    __shared__ float Bs[BK][BN + 4];

    const int b = blockIdx.z;
    A  += (size_t)b * sA;
    Bm += (size_t)b * sB;
    C  += (size_t)b * sC;

    const int m0 = blockIdx.y * BM;
    const int n0 = blockIdx.x * BN;
    const int tid = threadIdx.x;
    const int tx = tid & 15;
    const int ty = tid >> 4;
    const int arow = tid >> 2;
    const int acol = (tid & 3) * 4;
    const int brow = tid >> 4;
    const int bcol = (tid & 15) * 4;

    unsigned long long acc[4][4];
    #pragma unroll
    for (int r = 0; r < 4; r++)
        #pragma unroll
        for (int j = 0; j < 4; j++) acc[r][j] = 0ULL;

    float4 a0, a1v, bv;
    a0  = *(const float4*)(A + (size_t)(m0 + arow)      * K + acol);
    a1v = *(const float4*)(A + (size_t)(m0 + arow + 64) * K + acol);
    if (!TRANSB) bv = *(const float4*)(Bm + (size_t)brow * N + n0 + bcol);
    else         bv = *(const float4*)(Bm + (size_t)(n0 + arow) * K + acol);

    for (int k0 = 0; k0 < K; k0 += BK) {
        As[acol+0][arow]    = a0.x;  As[acol+1][arow]    = a0.y;
        As[acol+2][arow]    = a0.z;  As[acol+3][arow]    = a0.w;
        As[acol+0][arow+64] = a1v.x; As[acol+1][arow+64] = a1v.y;
        As[acol+2][arow+64] = a1v.z; As[acol+3][arow+64] = a1v.w;
        if (!TRANSB) {
            Bs[brow][bcol+0] = bv.x; Bs[brow][bcol+1] = bv.y;
            Bs[brow][bcol+2] = bv.z; Bs[brow][bcol+3] = bv.w;
        } else {
            Bs[acol+0][arow] = bv.x; Bs[acol+1][arow] = bv.y;
            Bs[acol+2][arow] = bv.z; Bs[acol+3][arow] = bv.w;
        }
        __syncthreads();

        const int kn = k0 + BK;
        if (kn < K) {
            a0  = *(const float4*)(A + (size_t)(m0 + arow)      * K + kn + acol);
            a1v = *(const float4*)(A + (size_t)(m0 + arow + 64) * K + kn + acol);
            if (!TRANSB) bv = *(const float4*)(Bm + (size_t)(kn + brow) * N + n0 + bcol);
            else         bv = *(const float4*)(Bm + (size_t)(n0 + arow) * K + kn + acol);
        }

        #pragma unroll
        for (int k = 0; k < BK; k++) {
            unsigned long long pa0, pa1, pa2, pa3;
            lds_v2u64(pa0, pa1, &As[k][ty * 8]);
            lds_v2u64(pa2, pa3, &As[k][ty * 8 + 4]);
            float4 rb = *(const float4*)&Bs[k][tx * 4];
            unsigned long long pb0 = splat2(rb.x), pb1 = splat2(rb.y);
            unsigned long long pb2 = splat2(rb.z), pb3 = splat2(rb.w);

            fma2(acc[0][0], pa0, pb0); fma2(acc[0][1], pa0, pb1);
            fma2(acc[0][2], pa0, pb2); fma2(acc[0][3], pa0, pb3);
            fma2(acc[1][0], pa1, pb0); fma2(acc[1][1], pa1, pb1);
            fma2(acc[1][2], pa1, pb2); fma2(acc[1][3], pa1, pb3);
            fma2(acc[2][0], pa2, pb0); fma2(acc[2][1], pa2, pb1);
            fma2(acc[2][2], pa2, pb2); fma2(acc[2][3], pa2, pb3);
            fma2(acc[3][0], pa3, pb0); fma2(acc[3][1], pa3, pb1);
            fma2(acc[3][2], pa3, pb2); fma2(acc[3][3], pa3, pb3);
        }
        __syncthreads();
    }

    const int nbase = n0 + tx * 4;
    #pragma unroll
    for (int r = 0; r < 4; r++) {
        float2 c0 = unpack2(acc[r][0]);
        float2 c1 = unpack2(acc[r][1]);
        float2 c2 = unpack2(acc[r][2]);
        float2 c3 = unpack2(acc[r][3]);
        float4 row_lo = make_float4(c0.x, c1.x, c2.x, c3.x);
        float4 row_hi = make_float4(c0.y, c1.y, c2.y, c3.y);
        const int m_lo = m0 + ty * 8 + 2 * r;
        *(float4*)(C + (size_t)m_lo       * N + nbase) = row_lo;
        *(float4*)(C + (size_t)(m_lo + 1) * N + nbase) = row_hi;
    }
}

// ---------------- HMMA GEMM: C = A @ B^T (bf16 3-pass split) ---------------
// CTA tile 128(M) x 128(N), 256 threads = 8 warps (4m x 2n), warp tile 32x64.
// A = [MA,K] row-major hi/lo, B = [NB,K] K-contig hi/lo, batch b via blockIdx.z.
// EPI==0: plain fp32 store (ldc = NB_total). EPI==1: scores epilogue.
#define AGG_ROWB  80                   // smem row stride in bytes (40 bf16)
#define AGG_ARR   10240                // one 128x40-bf16 array
#define AGG_BUF   (4*AGG_ARR)          // Ah,Al,Bh,Bl
#define AGG_SMEM  (2*AGG_BUF)          // double buffer = 80 KB

template<int EPI>
__global__ void __launch_bounds__(256)
mma_gemm_k(const __nv_bfloat16* __restrict__ Ah, const __nv_bfloat16* __restrict__ Al,
           const __nv_bfloat16* __restrict__ Bh, const __nv_bfloat16* __restrict__ Bl,
           float* __restrict__ C, int K, int MA, int NB, int ldc,
           const float* __restrict__ Ax, const float* __restrict__ Ay,
           const int* __restrict__ adj)
{
    extern __shared__ char smem[];
    const uint32_t sbase = smem_u32(smem);
    const int tid  = threadIdx.x;
    const int wid  = tid >> 5;
    const int lane = tid & 31;
    const int b  = blockIdx.z;
    const int m0 = blockIdx.y * 128;
    const int n0 = blockIdx.x * 128;

    // loader mapping: 64 rows x 4 segs; each thread rows {r, r+64}, 16B each
    const int r   = tid >> 2;
    const int seg = tid & 3;
    const __nv_bfloat16* gAh = Ah + ((size_t)b * MA + m0 + r) * K + seg * 8;
    const __nv_bfloat16* gAl = Al + ((size_t)b * MA + m0 + r) * K + seg * 8;
    const __nv_bfloat16* gBh = Bh + ((size_t)b * NB + n0 + r) * K + seg * 8;
    const __nv_bfloat16* gBl = Bl + ((size_t)b * NB + n0 + r) * K + seg * 8;
    const uint32_t sA = r * AGG_ROWB + seg * 16;
    const size_t  gstep = (size_t)64 * K;

    #define AGG_ISSUE(bufi, kc) do {                                           \
        const int kofs = (kc) * 32;                                            \
        uint32_t s0 = sbase + (bufi) * AGG_BUF + sA;                            \
        cp16(s0 + 0*AGG_ARR,               gAh + kofs);                         \
        cp16(s0 + 1*AGG_ARR,               gAl + kofs);                         \
        cp16(s0 + 2*AGG_ARR,               gBh + kofs);                         \
        cp16(s0 + 3*AGG_ARR,               gBl + kofs);                         \
        uint32_t s1 = s0 + 64 * AGG_ROWB;                                       \
        cp16(s1 + 0*AGG_ARR,               gAh + gstep + kofs);                 \
        cp16(s1 + 1*AGG_ARR,               gAl + gstep + kofs);                 \
        cp16(s1 + 2*AGG_ARR,               gBh + gstep + kofs);                 \
        cp16(s1 + 3*AGG_ARR,               gBl + gstep + kofs);                 \
        asm volatile("cp.async.commit_group;" ::: "memory");                    \
    } while (0)

    const int wm = wid & 3;    // 4 m-warps: rows wm*32..+32
    const int wn = wid >> 2;   // 2 n-warps: cols wn*64..+64

    float acc[2][8][4];
    #pragma unroll
    for (int mi = 0; mi < 2; mi++)
        #pragma unroll
        for (int nj = 0; nj < 8; nj++)
            #pragma unroll
            for (int q = 0; q < 4; q++) acc[mi][nj][q] = 0.f;

    const int NC = K / 32;
    AGG_ISSUE(0, 0);
    int buf = 0;
    for (int kc = 0; kc < NC; kc++) {
        if (kc + 1 < NC) {
            AGG_ISSUE(buf ^ 1, kc + 1);
            asm volatile("cp.async.wait_group 1;" ::: "memory");
        } else {
            asm volatile("cp.async.wait_group 0;" ::: "memory");
        }
        __syncthreads();

        const uint32_t base = sbase + buf * AGG_BUF;
        #pragma unroll
        for (int kq = 0; kq < 2; kq++) {
            const uint32_t aaddr = base
                + (uint32_t)((wm * 32 + (lane & 15)) * AGG_ROWB)
                + (uint32_t)((kq * 16 + (lane >> 4) * 8) * 2);
            uint32_t ah0[4], ah1[4], al0[4], al1[4];
            ldmx4(ah0, aaddr);
            ldmx4(ah1, aaddr + 16 * AGG_ROWB);
            ldmx4(al0, aaddr + 1*AGG_ARR);
            ldmx4(al1, aaddr + 1*AGG_ARR + 16 * AGG_ROWB);

            #pragma unroll
            for (int np = 0; np < 4; np++) {
                const uint32_t baddr = base + 2*AGG_ARR
                    + (uint32_t)((wn * 64 + np * 16 + (lane & 7) + ((lane >> 4) << 3)) * AGG_ROWB)
                    + (uint32_t)((kq * 16 + ((lane >> 3) & 1) * 8) * 2);
                uint32_t bh[4], bl[4];
                ldmx4(bh, baddr);
                ldmx4(bl, baddr + 1*AGG_ARR);
                const int j0 = np * 2, j1 = np * 2 + 1;
                mma_bf16(acc[0][j0], ah0, bh[0], bh[1]);
                mma_bf16(acc[0][j1], ah0, bh[2], bh[3]);
                mma_bf16(acc[1][j0], ah1, bh[0], bh[1]);
                mma_bf16(acc[1][j1], ah1, bh[2], bh[3]);
                mma_bf16(acc[0][j0], ah0, bl[0], bl[1]);
                mma_bf16(acc[0][j1], ah0, bl[2], bl[3]);
                mma_bf16(acc[1][j0], ah1, bl[0], bl[1]);
                mma_bf16(acc[1][j1], ah1, bl[2], bl[3]);
                mma_bf16(acc[0][j0], al0, bh[0], bh[1]);
                mma_bf16(acc[0][j1], al0, bh[2], bh[3]);
                mma_bf16(acc[1][j0], al1, bh[0], bh[1]);
                mma_bf16(acc[1][j1], al1, bh[2], bh[3]);
            }
        }
        __syncthreads();
        buf ^= 1;
    }
    #undef AGG_ISSUE

    // epilogue
    const int mbase = m0 + wm * 32;
    const int nbase = n0 + wn * 64;
    #pragma unroll
    for (int mi = 0; mi < 2; mi++) {
        #pragma unroll
        for (int nj = 0; nj < 8; nj++) {
            const int mm = mbase + mi * 16 + (lane >> 2);
            const int nc = nbase + nj * 8 + (lane & 3) * 2;
            float* d0 = C + ((size_t)b * MA + mm) * ldc + nc;
            if (EPI == 0) {
                *(float2*)d0              = make_float2(acc[mi][nj][0], acc[mi][nj][1]);
                *(float2*)(d0 + 8 * ldc)  = make_float2(acc[mi][nj][2], acc[mi][nj][3]);
            } else {
                const float2 axv = *(const float2*)(Ax + b * NN + nc);
                const float ay0 = Ay[b * NN + mm];
                const float ay1 = Ay[b * NN + mm + 8];
                float2 v0 = make_float2(lrelu(acc[mi][nj][0] + ay0 + axv.x),
                                        lrelu(acc[mi][nj][1] + ay0 + axv.y));
                float2 v1 = make_float2(lrelu(acc[mi][nj][2] + ay1 + axv.x),
                                        lrelu(acc[mi][nj][3] + ay1 + axv.y));
                const int* adp = adj + ((size_t)b * NN + mm) * NN + nc;
                int2 a0v = *(const int2*)adp;
                int2 a1v = *(const int2*)(adp + 8 * NN);
                v0.x = (a0v.x > 0) ? v0.x : NEGc;
                v0.y = (a0v.y > 0) ? v0.y : NEGc;
                v1.x = (a1v.x > 0) ? v1.x : NEGc;
                v1.y = (a1v.y > 0) ? v1.y : NEGc;
                *(float2*)d0             = v0;
                *(float2*)(d0 + 8 * ldc) = v1;
            }
        }
    }
}

// --------- fp32 -> bf16 hi/lo elementwise split ------------------------------
__global__ void split_k(const float* __restrict__ src,
                        __nv_bfloat16* __restrict__ hi,
                        __nv_bfloat16* __restrict__ lo, size_t n4)
{
    const size_t i = (size_t)blockIdx.x * blockDim.x + threadIdx.x;
    if (i >= n4) return;
    const float4 v = ((const float4*)src)[i];
    __nv_bfloat16 h0 = __float2bfloat16_rn(v.x);
    __nv_bfloat16 h1 = __float2bfloat16_rn(v.y);
    __nv_bfloat16 h2 = __float2bfloat16_rn(v.z);
    __nv_bfloat16 h3 = __float2bfloat16_rn(v.w);
    __nv_bfloat162 H0 = {h0, h1}, H1 = {h2, h3};
    __nv_bfloat162 L0 = {__float2bfloat16_rn(v.x - __bfloat162float(h0)),
                         __float2bfloat16_rn(v.y - __bfloat162float(h1))};
    __nv_bfloat162 L1 = {__float2bfloat16_rn(v.z - __bfloat162float(h2)),
                         __float2bfloat16_rn(v.w - __bfloat162float(h3))};
    ((__nv_bfloat162*)hi)[i*2]   = H0;
    ((__nv_bfloat162*)hi)[i*2+1] = H1;
    ((__nv_bfloat162*)lo)[i*2]   = L0;
    ((__nv_bfloat162*)lo)[i*2+1] = L1;
}

// --------- transpose + bf16 split: featT_hi/lo[b][f][n] = split(feat[b][n][f])
__global__ void transpose_split_k(const float* __restrict__ feat,
                                  __nv_bfloat16* __restrict__ Fhi,
                                  __nv_bfloat16* __restrict__ Flo)
{
    __shared__ float t[32][33];
    const int b  = blockIdx.z;
    const int n0 = blockIdx.x * 32;
    const int f0 = blockIdx.y * 32;
    const int tx = threadIdx.x, ty = threadIdx.y;   // (32, 8)

    #pragma unroll
    for (int i = 0; i < 4; i++)
        t[ty + 8*i][tx] = feat[((size_t)b * NN + n0 + ty + 8*i) * FINx + f0 + tx];
    __syncthreads();
    #pragma unroll
    for (int i = 0; i < 4; i++) {
        const float v = t[tx][ty + 8*i];
        const __nv_bfloat16 hi = __float2bfloat16_rn(v);
        const __nv_bfloat16 lo = __float2bfloat16_rn(v - __bfloat162float(hi));
        const size_t idx = ((size_t)b * FINx + f0 + ty + 8*i) * NN + n0 + tx;
        Fhi[idx] = hi;
        Flo[idx] = lo;
    }
}

// --------- Ax = h@a1, Ay = h@a2, e1[e] = feat row . L_w[e] (warp/row) -------
__global__ void small1_k(const float* __restrict__ h, const float* __restrict__ feat,
                         const float* __restrict__ a1, const float* __restrict__ a2,
                         const float* __restrict__ Lw,
                         float* __restrict__ Ax, float* __restrict__ Ay,
                         float* __restrict__ e1)
{
    const int warp = (blockIdx.x * blockDim.x + threadIdx.x) >> 5;
    const int lane = threadIdx.x & 31;
    if (warp >= MTOT) return;

    const float* hr = h + (size_t)warp * FOUTx;
    float sx = 0.f, sy = 0.f;
    for (int k = lane; k < FOUTx; k += 32) {
        const float f = hr[k];
        sx += f * a1[k];
        sy += f * a2[k];
    }
    const float* fr = feat + (size_t)warp * FINx;
    float acc[5] = {0.f, 0.f, 0.f, 0.f, 0.f};
    for (int k = lane; k < FINx; k += 32) {
        const float f = fr[k];
        #pragma unroll
        for (int e = 0; e < 5; e++) acc[e] += f * Lw[e * FINx + k];
    }
    #pragma unroll
    for (int off = 16; off; off >>= 1) {
        sx += __shfl_xor_sync(0xffffffffu, sx, off);
        sy += __shfl_xor_sync(0xffffffffu, sy, off);
        #pragma unroll
        for (int e = 0; e < 5; e++) acc[e] += __shfl_xor_sync(0xffffffffu, acc[e], off);
    }
    if (lane == 0) {
        Ax[warp] = sx;
        Ay[warp] = sy;
        #pragma unroll
        for (int e = 0; e < 5; e++) e1[warp * 8 + e] = acc[e];
    }
}

// --------- e2[e] = feat_agg row . R_w[e] -----------------------------------
__global__ void small2_k(const float* __restrict__ fa, const float* __restrict__ Rw,
                         float* __restrict__ e2)
{
    const int warp = (blockIdx.x * blockDim.x + threadIdx.x) >> 5;
    const int lane = threadIdx.x & 31;
    if (warp >= MTOT) return;

    const float* fr = fa + (size_t)warp * FINx;
    float acc[5] = {0.f, 0.f, 0.f, 0.f, 0.f};
    for (int k = lane; k < FINx; k += 32) {
        const float f = fr[k];
        #pragma unroll
        for (int e = 0; e < 5; e++) acc[e] += f * Rw[e * FINx + k];
    }
    #pragma unroll
    for (int off = 16; off; off >>= 1) {
        #pragma unroll
        for (int e = 0; e < 5; e++) acc[e] += __shfl_xor_sync(0xffffffffu, acc[e], off);
    }
    if (lane == 0) {
        #pragma unroll
        for (int e = 0; e < 5; e++) e2[warp * 8 + e] = acc[e];
    }
}

// --------- row softmax over N=2048 -> bf16 hi/lo probs ----------------------
__global__ void __launch_bounds__(256)
softmax_k(const float* __restrict__ S,
          __nv_bfloat16* __restrict__ Phi, __nv_bfloat16* __restrict__ Plo)
{
    const float* p = S + (size_t)blockIdx.x * NN;
    const int t = threadIdx.x;
    float v[8];
    float mx = -3.4e38f;
    #pragma unroll
    for (int i = 0; i < 8; i++) { v[i] = p[t + i * 256]; mx = fmaxf(mx, v[i]); }

    __shared__ float red[256];
    red[t] = mx; __syncthreads();
    #pragma unroll
    for (int s = 128; s > 0; s >>= 1) {
        if (t < s) red[t] = fmaxf(red[t], red[t + s]);
        __syncthreads();
    }
    mx = red[0];
    __syncthreads();

    float sum = 0.f;
    #pragma unroll
    for (int i = 0; i < 8; i++) { v[i] = __expf(v[i] - mx); sum += v[i]; }
    red[t] = sum; __syncthreads();
    #pragma unroll
    for (int s = 128; s > 0; s >>= 1) {
        if (t < s) red[t] += red[t + s];
        __syncthreads();
    }
    const float inv = 1.0f / red[0];
    __nv_bfloat16* ph = Phi + (size_t)blockIdx.x * NN;
    __nv_bfloat16* pl = Plo + (size_t)blockIdx.x * NN;
    #pragma unroll
    for (int i = 0; i < 8; i++) {
        const float pv = v[i] * inv;
        const __nv_bfloat16 hi = __float2bfloat16_rn(pv);
        const __nv_bfloat16 lo = __float2bfloat16_rn(pv - __bfloat162float(hi));
        ph[t + i * 256] = hi;
        pl[t + i * 256] = lo;
    }
}

// --------- out = h1 + h2 + e1^T B_w[o] e2 ----------------------------------
__global__ void __launch_bounds__(256)
final_k(const float* __restrict__ h1, const float* __restrict__ h2,
        const float* __restrict__ e1, const float* __restrict__ e2,
        const float* __restrict__ Bw, float* __restrict__ out)
{
    const int m = blockIdx.x;
    const int o = threadIdx.x;   // 0..255
    __shared__ float s1[8], s2[8];
    if (o < 5) { s1[o] = e1[m * 8 + o]; s2[o] = e2[m * 8 + o]; }
    __syncthreads();

    const float* bw = Bw + o * 25;
    float s = 0.f;
    #pragma unroll
    for (int i = 0; i < 5; i++) {
        const float ei = s1[i];
        #pragma unroll
        for (int j = 0; j < 5; j++) s += ei * bw[i * 5 + j] * s2[j];
    }
    const size_t idx = (size_t)m * FOUTx + o;
    out[idx] = h1[idx] + h2[idx] + s;
}

// ---------------------------------------------------------------------------
extern "C" void kernel_launch(void* const* d_in, const int* in_sizes, int n_in,
                              void* d_out, int out_size)
{
    const float* feat = (const float*)d_in[0];
    const int*   adj  = (const int*)  d_in[1];
    const float* W    = (const float*)d_in[2];
    const float* W1   = (const float*)d_in[3];
    const float* W2   = (const float*)d_in[4];
    const float* a1   = (const float*)d_in[5];
    const float* a2   = (const float*)d_in[6];
    const float* a12  = (const float*)d_in[7];
    const float* Lw   = (const float*)d_in[8];
    const float* Rw   = (const float*)d_in[9];
    const float* Bw   = (const float*)d_in[10];
    float* out = (float*)d_out;

    float *h, *h1, *g, *h2, *Ax, *Ay, *e1, *e2, *S, *fa;
    __nv_bfloat16 *Shi, *Slo, *Fhi, *Flo, *ghi, *glo, *hhi, *hlo;
    cudaGetSymbolAddress((void**)&h,  g_h);
    cudaGetSymbolAddress((void**)&h1, g_h1);
    cudaGetSymbolAddress((void**)&g,  g_g);
    cudaGetSymbolAddress((void**)&h2, g_h2);
    cudaGetSymbolAddress((void**)&Ax, g_Ax);
    cudaGetSymbolAddress((void**)&Ay, g_Ay);
    cudaGetSymbolAddress((void**)&e1, g_e1);
    cudaGetSymbolAddress((void**)&e2, g_e2);
    cudaGetSymbolAddress((void**)&S,  g_S);
    cudaGetSymbolAddress((void**)&fa, g_fa);
    cudaGetSymbolAddress((void**)&Shi, g_Shi);
    cudaGetSymbolAddress((void**)&Slo, g_Slo);
    cudaGetSymbolAddress((void**)&Fhi, g_Fhi);
    cudaGetSymbolAddress((void**)&Flo, g_Flo);
    cudaGetSymbolAddress((void**)&ghi, g_ghi);
    cudaGetSymbolAddress((void**)&glo, g_glo);
    cudaGetSymbolAddress((void**)&hhi, g_hhi);
    cudaGetSymbolAddress((void**)&hlo, g_hlo);

    static int smem_set = 0;
    if (!smem_set) {
        cudaFuncSetAttribute(mma_gemm_k<0>, cudaFuncAttributeMaxDynamicSharedMemorySize,
                             AGG_SMEM);
        cudaFuncSetAttribute(mma_gemm_k<1>, cudaFuncAttributeMaxDynamicSharedMemorySize,
                             AGG_SMEM);
        smem_set = 1;
    }

    const dim3 blk(256);

    // featT hi/lo split (independent of everything else)
    transpose_split_k<<<dim3(NN/32, FINx/32, Bn), dim3(32, 8)>>>(feat, Fhi, Flo);

    // h = feat @ W ; h1 = feat @ W1
    gemm_k<false,0><<<dim3(FOUTx/64, MTOT/128, 1), blk>>>(
        feat, W,  h,  MTOT, FOUTx, FINx, 0, 0, 0, nullptr, nullptr, nullptr);
    gemm_k<false,0><<<dim3(FOUTx/64, MTOT/128, 1), blk>>>(
        feat, W1, h1, MTOT, FOUTx, FINx, 0, 0, 0, nullptr, nullptr, nullptr);

    // Ax, Ay, e1
    small1_k<<<MTOT/8, 256>>>(h, feat, a1, a2, Lw, Ax, Ay, e1);

    // g = h @ a12
    gemm_k<false,0><<<dim3(FOUTx/64, MTOT/128, 1), blk>>>(
        h, a12, g, MTOT, FOUTx, FOUTx, 0, 0, 0, nullptr, nullptr, nullptr);

    // bf16 hi/lo splits of g and h (operands for scores HMMA)
    {
        const size_t n4 = (size_t)MTOT * FOUTx / 4;
        split_k<<<(unsigned)((n4 + 255) / 256), 256>>>(g, ghi, glo, n4);
        split_k<<<(unsigned)((n4 + 255) / 256), 256>>>(h, hhi, hlo, n4);
    }

    // S[b,i,j] = leaky(Ax[j]+Ay[i]+g_i.h_j) masked by adj  (HMMA, bf16 split x3)
    mma_gemm_k<1><<<dim3(NN/128, NN/128, Bn), blk, AGG_SMEM>>>(
        ghi, glo, hhi, hlo, S, FOUTx, NN, NN, NN, Ax, Ay, adj);

    // row softmax -> bf16 hi/lo probs
    softmax_k<<<MTOT, 256>>>(S, Shi, Slo);

    // feat_agg = P @ feat  (HMMA, bf16 split x3)
    mma_gemm_k<0><<<dim3(FINx/128, NN/128, Bn), blk, AGG_SMEM>>>(
        Shi, Slo, Fhi, Flo, fa, NN, NN, FINx, FINx, nullptr, nullptr, nullptr);

    // e2
    small2_k<<<MTOT/8, 256>>>(fa, Rw, e2);

    // h2 = feat_agg @ W2
    gemm_k<false,0><<<dim3(FOUTx/64, MTOT/128, 1), blk>>>(
        fa, W2, h2, MTOT, FOUTx, FINx, 0, 0, 0, nullptr, nullptr, nullptr);

    // out = h1 + h2 + bilinear(e1, B_w, e2)
    final_k<<<MTOT, 256>>>(h1, h2, e1, e2, Bw, out);
}

// round 12
// speedup vs baseline: 1.8698x; 1.1869x over previous
#include <cuda_runtime.h>
#include <cuda_bf16.h>
#include <cstdint>

// Problem constants
#define Bn    8
#define NN    2048
#define FINx  512
#define FOUTx 256
#define MTOT  (Bn*NN)          // 16384
#define ALPHAc 0.2f
#define NEGc  (-9e15f)

// ---------------- scratch (device globals: allocation-free) ----------------
__device__ float g_h [MTOT*FOUTx];            // feat@W
__device__ float g_h1[MTOT*FOUTx];            // feat@W1
__device__ float g_g [MTOT*FOUTx];            // h@a12
__device__ float g_h2[MTOT*FOUTx];            // fa@W2
__device__ float g_Ax[MTOT];
__device__ float g_Ay[MTOT];
__device__ float g_e1[MTOT*8];
__device__ float g_e2[MTOT*8];
__device__ float g_S [(size_t)Bn*NN*NN];      // logits (134 MB)
__device__ __nv_bfloat16 g_Shi[(size_t)Bn*NN*NN];   // probs hi (67 MB)
__device__ __nv_bfloat16 g_Slo[(size_t)Bn*NN*NN];   // probs lo (67 MB)
__device__ __nv_bfloat16 g_Fhi[(size_t)Bn*FINx*NN]; // featT hi (16 MB)
__device__ __nv_bfloat16 g_Flo[(size_t)Bn*FINx*NN]; // featT lo (16 MB)
__device__ __nv_bfloat16 g_fRhi[(size_t)MTOT*FINx]; // feat row-major hi
__device__ __nv_bfloat16 g_fRlo[(size_t)MTOT*FINx];
__device__ __nv_bfloat16 g_fahi[(size_t)MTOT*FINx]; // fa hi
__device__ __nv_bfloat16 g_falo[(size_t)MTOT*FINx];
__device__ __nv_bfloat16 g_ghi[MTOT*FOUTx];   // g hi
__device__ __nv_bfloat16 g_glo[MTOT*FOUTx];
__device__ __nv_bfloat16 g_hhi[MTOT*FOUTx];   // h hi
__device__ __nv_bfloat16 g_hlo[MTOT*FOUTx];
__device__ __nv_bfloat16 g_Wth [FOUTx*FINx];  // W^T hi/lo
__device__ __nv_bfloat16 g_Wtl [FOUTx*FINx];
__device__ __nv_bfloat16 g_W1th[FOUTx*FINx];
__device__ __nv_bfloat16 g_W1tl[FOUTx*FINx];
__device__ __nv_bfloat16 g_W2th[FOUTx*FINx];
__device__ __nv_bfloat16 g_W2tl[FOUTx*FINx];
__device__ __nv_bfloat16 g_a12th[FOUTx*FOUTx];
__device__ __nv_bfloat16 g_a12tl[FOUTx*FOUTx];
__device__ float g_fa[(size_t)MTOT*FINx];     // feat_agg

// ---------------- mma.sync / cp.async helpers (sm_80+) ----------------------
__device__ __forceinline__ uint32_t smem_u32(const void* p) {
    return (uint32_t)__cvta_generic_to_shared(p);
}
__device__ __forceinline__ void cp16(uint32_t s, const void* g) {
    asm volatile("cp.async.cg.shared.global [%0], [%1], 16;" :: "r"(s), "l"(g));
}
__device__ __forceinline__ void ldmx4(uint32_t* d, uint32_t a) {
    asm volatile("ldmatrix.sync.aligned.m8n8.x4.shared.b16 {%0,%1,%2,%3}, [%4];"
                 : "=r"(d[0]), "=r"(d[1]), "=r"(d[2]), "=r"(d[3]) : "r"(a));
}
__device__ __forceinline__ void mma_bf16(float* c, const uint32_t* a,
                                         uint32_t b0, uint32_t b1) {
    asm volatile("mma.sync.aligned.m16n8k16.row.col.f32.bf16.bf16.f32 "
                 "{%0,%1,%2,%3}, {%4,%5,%6,%7}, {%8,%9}, {%0,%1,%2,%3};"
                 : "+f"(c[0]), "+f"(c[1]), "+f"(c[2]), "+f"(c[3])
                 : "r"(a[0]), "r"(a[1]), "r"(a[2]), "r"(a[3]), "r"(b0), "r"(b1));
}
__device__ __forceinline__ float lrelu(float v) {
    return (v > 0.f) ? v : ALPHAc * v;
}

// ---------------- HMMA GEMM: C = A @ B^T (bf16 3-pass split) ---------------
// CTA tile 128(M) x 128(N), 256 threads = 8 warps (4m x 2n), warp tile 32x64.
// A = [MA,K] row-major hi/lo, B = [NB,K] K-contig hi/lo, batch via blockIdx.z.
// EPI==0: plain fp32 store. EPI==1: scores epilogue.
#define AGG_ROWB  80                   // smem row stride in bytes (40 bf16)
#define AGG_ARR   10240                // one 128x40-bf16 array
#define AGG_BUF   (4*AGG_ARR)          // Ah,Al,Bh,Bl
#define AGG_SMEM  (2*AGG_BUF)          // double buffer = 80 KB

template<int EPI>
__global__ void __launch_bounds__(256)
mma_gemm_k(const __nv_bfloat16* __restrict__ Ah, const __nv_bfloat16* __restrict__ Al,
           const __nv_bfloat16* __restrict__ Bh, const __nv_bfloat16* __restrict__ Bl,
           float* __restrict__ C, int K, int MA, int NB, int ldc,
           const float* __restrict__ Ax, const float* __restrict__ Ay,
           const int* __restrict__ adj)
{
    extern __shared__ char smem[];
    const uint32_t sbase = smem_u32(smem);
    const int tid  = threadIdx.x;
    const int wid  = tid >> 5;
    const int lane = tid & 31;
    const int b  = blockIdx.z;
    const int m0 = blockIdx.y * 128;
    const int n0 = blockIdx.x * 128;

    // loader mapping: 64 rows x 4 segs; each thread rows {r, r+64}, 16B each
    const int r   = tid >> 2;
    const int seg = tid & 3;
    const __nv_bfloat16* gAh = Ah + ((size_t)b * MA + m0 + r) * K + seg * 8;
    const __nv_bfloat16* gAl = Al + ((size_t)b * MA + m0 + r) * K + seg * 8;
    const __nv_bfloat16* gBh = Bh + ((size_t)b * NB + n0 + r) * K + seg * 8;
    const __nv_bfloat16* gBl = Bl + ((size_t)b * NB + n0 + r) * K + seg * 8;
    const uint32_t sA = r * AGG_ROWB + seg * 16;
    const size_t  gstep = (size_t)64 * K;

    #define AGG_ISSUE(bufi, kc) do {                                           \
        const int kofs = (kc) * 32;                                            \
        uint32_t s0 = sbase + (bufi) * AGG_BUF + sA;                            \
        cp16(s0 + 0*AGG_ARR,               gAh + kofs);                         \
        cp16(s0 + 1*AGG_ARR,               gAl + kofs);                         \
        cp16(s0 + 2*AGG_ARR,               gBh + kofs);                         \
        cp16(s0 + 3*AGG_ARR,               gBl + kofs);                         \
        uint32_t s1 = s0 + 64 * AGG_ROWB;                                       \
        cp16(s1 + 0*AGG_ARR,               gAh + gstep + kofs);                 \
        cp16(s1 + 1*AGG_ARR,               gAl + gstep + kofs);                 \
        cp16(s1 + 2*AGG_ARR,               gBh + gstep + kofs);                 \
        cp16(s1 + 3*AGG_ARR,               gBl + gstep + kofs);                 \
        asm volatile("cp.async.commit_group;" ::: "memory");                    \
    } while (0)

    const int wm = wid & 3;    // 4 m-warps
    const int wn = wid >> 2;   // 2 n-warps

    float acc[2][8][4];
    #pragma unroll
    for (int mi = 0; mi < 2; mi++)
        #pragma unroll
        for (int nj = 0; nj < 8; nj++)
            #pragma unroll
            for (int q = 0; q < 4; q++) acc[mi][nj][q] = 0.f;

    const int NC = K / 32;
    AGG_ISSUE(0, 0);
    int buf = 0;
    for (int kc = 0; kc < NC; kc++) {
        if (kc + 1 < NC) {
            AGG_ISSUE(buf ^ 1, kc + 1);
            asm volatile("cp.async.wait_group 1;" ::: "memory");
        } else {
            asm volatile("cp.async.wait_group 0;" ::: "memory");
        }
        __syncthreads();

        const uint32_t base = sbase + buf * AGG_BUF;
        #pragma unroll
        for (int kq = 0; kq < 2; kq++) {
            const uint32_t aaddr = base
                + (uint32_t)((wm * 32 + (lane & 15)) * AGG_ROWB)
                + (uint32_t)((kq * 16 + (lane >> 4) * 8) * 2);
            uint32_t ah0[4], ah1[4], al0[4], al1[4];
            ldmx4(ah0, aaddr);
            ldmx4(ah1, aaddr + 16 * AGG_ROWB);
            ldmx4(al0, aaddr + 1*AGG_ARR);
            ldmx4(al1, aaddr + 1*AGG_ARR + 16 * AGG_ROWB);

            #pragma unroll
            for (int np = 0; np < 4; np++) {
                const uint32_t baddr = base + 2*AGG_ARR
                    + (uint32_t)((wn * 64 + np * 16 + (lane & 7) + ((lane >> 4) << 3)) * AGG_ROWB)
                    + (uint32_t)((kq * 16 + ((lane >> 3) & 1) * 8) * 2);
                uint32_t bh[4], bl[4];
                ldmx4(bh, baddr);
                ldmx4(bl, baddr + 1*AGG_ARR);
                const int j0 = np * 2, j1 = np * 2 + 1;
                mma_bf16(acc[0][j0], ah0, bh[0], bh[1]);
                mma_bf16(acc[0][j1], ah0, bh[2], bh[3]);
                mma_bf16(acc[1][j0], ah1, bh[0], bh[1]);
                mma_bf16(acc[1][j1], ah1, bh[2], bh[3]);
                mma_bf16(acc[0][j0], ah0, bl[0], bl[1]);
                mma_bf16(acc[0][j1], ah0, bl[2], bl[3]);
                mma_bf16(acc[1][j0], ah1, bl[0], bl[1]);
                mma_bf16(acc[1][j1], ah1, bl[2], bl[3]);
                mma_bf16(acc[0][j0], al0, bh[0], bh[1]);
                mma_bf16(acc[0][j1], al0, bh[2], bh[3]);
                mma_bf16(acc[1][j0], al1, bh[0], bh[1]);
                mma_bf16(acc[1][j1], al1, bh[2], bh[3]);
            }
        }
        __syncthreads();
        buf ^= 1;
    }
    #undef AGG_ISSUE

    // epilogue
    const int mbase = m0 + wm * 32;
    const int nbase = n0 + wn * 64;
    #pragma unroll
    for (int mi = 0; mi < 2; mi++) {
        #pragma unroll
        for (int nj = 0; nj < 8; nj++) {
            const int mm = mbase + mi * 16 + (lane >> 2);
            const int nc = nbase + nj * 8 + (lane & 3) * 2;
            float* d0 = C + ((size_t)b * MA + mm) * ldc + nc;
            if (EPI == 0) {
                *(float2*)d0              = make_float2(acc[mi][nj][0], acc[mi][nj][1]);
                *(float2*)(d0 + 8 * ldc)  = make_float2(acc[mi][nj][2], acc[mi][nj][3]);
            } else {
                const float2 axv = *(const float2*)(Ax + b * NN + nc);
                const float ay0 = Ay[b * NN + mm];
                const float ay1 = Ay[b * NN + mm + 8];
                float2 v0 = make_float2(lrelu(acc[mi][nj][0] + ay0 + axv.x),
                                        lrelu(acc[mi][nj][1] + ay0 + axv.y));
                float2 v1 = make_float2(lrelu(acc[mi][nj][2] + ay1 + axv.x),
                                        lrelu(acc[mi][nj][3] + ay1 + axv.y));
                const int* adp = adj + ((size_t)b * NN + mm) * NN + nc;
                int2 a0v = *(const int2*)adp;
                int2 a1v = *(const int2*)(adp + 8 * NN);
                v0.x = (a0v.x > 0) ? v0.x : NEGc;
                v0.y = (a0v.y > 0) ? v0.y : NEGc;
                v1.x = (a1v.x > 0) ? v1.x : NEGc;
                v1.y = (a1v.y > 0) ? v1.y : NEGc;
                *(float2*)d0             = v0;
                *(float2*)(d0 + 8 * ldc) = v1;
            }
        }
    }
}

// --------- fp32 -> bf16 hi/lo elementwise split ------------------------------
__global__ void split_k(const float* __restrict__ src,
                        __nv_bfloat16* __restrict__ hi,
                        __nv_bfloat16* __restrict__ lo, size_t n4)
{
    const size_t i = (size_t)blockIdx.x * blockDim.x + threadIdx.x;
    if (i >= n4) return;
    const float4 v = ((const float4*)src)[i];
    __nv_bfloat16 h0 = __float2bfloat16_rn(v.x);
    __nv_bfloat16 h1 = __float2bfloat16_rn(v.y);
    __nv_bfloat16 h2 = __float2bfloat16_rn(v.z);
    __nv_bfloat16 h3 = __float2bfloat16_rn(v.w);
    __nv_bfloat162 H0 = {h0, h1}, H1 = {h2, h3};
    __nv_bfloat162 L0 = {__float2bfloat16_rn(v.x - __bfloat162float(h0)),
                         __float2bfloat16_rn(v.y - __bfloat162float(h1))};
    __nv_bfloat162 L1 = {__float2bfloat16_rn(v.z - __bfloat162float(h2)),
                         __float2bfloat16_rn(v.w - __bfloat162float(h3))};
    ((__nv_bfloat162*)hi)[i*2]   = H0;
    ((__nv_bfloat162*)hi)[i*2+1] = H1;
    ((__nv_bfloat162*)lo)[i*2]   = L0;
    ((__nv_bfloat162*)lo)[i*2+1] = L1;
}

// --------- generic transpose + split: dst[c][r] = split(src[r][c]) ----------
__global__ void tsplit_k(const float* __restrict__ src,
                         __nv_bfloat16* __restrict__ hi,
                         __nv_bfloat16* __restrict__ lo, int R, int C)
{
    __shared__ float t[32][33];
    const int r0 = blockIdx.y * 32;
    const int c0 = blockIdx.x * 32;
    const int tx = threadIdx.x, ty = threadIdx.y;   // (32, 8)
    #pragma unroll
    for (int i = 0; i < 4; i++)
        t[ty + 8*i][tx] = src[(size_t)(r0 + ty + 8*i) * C + c0 + tx];
    __syncthreads();
    #pragma unroll
    for (int i = 0; i < 4; i++) {
        const float v = t[tx][ty + 8*i];
        const __nv_bfloat16 h = __float2bfloat16_rn(v);
        const __nv_bfloat16 l = __float2bfloat16_rn(v - __bfloat162float(h));
        const size_t idx = (size_t)(c0 + ty + 8*i) * R + r0 + tx;
        hi[idx] = h;
        lo[idx] = l;
    }
}

// --------- batched transpose + split: featT[b][f][n] = split(feat[b][n][f]) -
__global__ void transpose_split_k(const float* __restrict__ feat,
                                  __nv_bfloat16* __restrict__ Fhi,
                                  __nv_bfloat16* __restrict__ Flo)
{
    __shared__ float t[32][33];
    const int b  = blockIdx.z;
    const int n0 = blockIdx.x * 32;
    const int f0 = blockIdx.y * 32;
    const int tx = threadIdx.x, ty = threadIdx.y;   // (32, 8)

    #pragma unroll
    for (int i = 0; i < 4; i++)
        t[ty + 8*i][tx] = feat[((size_t)b * NN + n0 + ty + 8*i) * FINx + f0 + tx];
    __syncthreads();
    #pragma unroll
    for (int i = 0; i < 4; i++) {
        const float v = t[tx][ty + 8*i];
        const __nv_bfloat16 hi = __float2bfloat16_rn(v);
        const __nv_bfloat16 lo = __float2bfloat16_rn(v - __bfloat162float(hi));
        const size_t idx = ((size_t)b * FINx + f0 + ty + 8*i) * NN + n0 + tx;
        Fhi[idx] = hi;
        Flo[idx] = lo;
    }
}

// --------- Ax = h@a1, Ay = h@a2, e1[e] = feat row . L_w[e] (warp/row) -------
__global__ void small1_k(const float* __restrict__ h, const float* __restrict__ feat,
                         const float* __restrict__ a1, const float* __restrict__ a2,
                         const float* __restrict__ Lw,
                         float* __restrict__ Ax, float* __restrict__ Ay,
                         float* __restrict__ e1)
{
    const int warp = (blockIdx.x * blockDim.x + threadIdx.x) >> 5;
    const int lane = threadIdx.x & 31;
    if (warp >= MTOT) return;

    const float4* hr  = (const float4*)(h + (size_t)warp * FOUTx);
    const float4* a14 = (const float4*)a1;
    const float4* a24 = (const float4*)a2;
    float sx = 0.f, sy = 0.f;
    #pragma unroll
    for (int c = 0; c < 2; c++) {
        const float4 f = hr[lane + c * 32];
        const float4 u = a14[lane + c * 32];
        const float4 w = a24[lane + c * 32];
        sx += f.x*u.x + f.y*u.y + f.z*u.z + f.w*u.w;
        sy += f.x*w.x + f.y*w.y + f.z*w.z + f.w*w.w;
    }
    const float4* fr  = (const float4*)(feat + (size_t)warp * FINx);
    const float4* Lw4 = (const float4*)Lw;
    float acc[5] = {0.f, 0.f, 0.f, 0.f, 0.f};
    #pragma unroll
    for (int c = 0; c < 4; c++) {
        const float4 f = fr[lane + c * 32];
        #pragma unroll
        for (int e = 0; e < 5; e++) {
            const float4 w = Lw4[e * 128 + lane + c * 32];
            acc[e] += f.x*w.x + f.y*w.y + f.z*w.z + f.w*w.w;
        }
    }
    #pragma unroll
    for (int off = 16; off; off >>= 1) {
        sx += __shfl_xor_sync(0xffffffffu, sx, off);
        sy += __shfl_xor_sync(0xffffffffu, sy, off);
        #pragma unroll
        for (int e = 0; e < 5; e++) acc[e] += __shfl_xor_sync(0xffffffffu, acc[e], off);
    }
    if (lane == 0) {
        Ax[warp] = sx;
        Ay[warp] = sy;
        #pragma unroll
        for (int e = 0; e < 5; e++) e1[warp * 8 + e] = acc[e];
    }
}

// --------- e2[e] = feat_agg row . R_w[e] -----------------------------------
__global__ void small2_k(const float* __restrict__ fa, const float* __restrict__ Rw,
                         float* __restrict__ e2)
{
    const int warp = (blockIdx.x * blockDim.x + threadIdx.x) >> 5;
    const int lane = threadIdx.x & 31;
    if (warp >= MTOT) return;

    const float4* fr  = (const float4*)(fa + (size_t)warp * FINx);
    const float4* Rw4 = (const float4*)Rw;
    float acc[5] = {0.f, 0.f, 0.f, 0.f, 0.f};
    #pragma unroll
    for (int c = 0; c < 4; c++) {
        const float4 f = fr[lane + c * 32];
        #pragma unroll
        for (int e = 0; e < 5; e++) {
            const float4 w = Rw4[e * 128 + lane + c * 32];
            acc[e] += f.x*w.x + f.y*w.y + f.z*w.z + f.w*w.w;
        }
    }
    #pragma unroll
    for (int off = 16; off; off >>= 1) {
        #pragma unroll
        for (int e = 0; e < 5; e++) acc[e] += __shfl_xor_sync(0xffffffffu, acc[e], off);
    }
    if (lane == 0) {
        #pragma unroll
        for (int e = 0; e < 5; e++) e2[warp * 8 + e] = acc[e];
    }
}

// --------- row softmax over N=2048 -> bf16 hi/lo probs ----------------------
__global__ void __launch_bounds__(256)
softmax_k(const float* __restrict__ S,
          __nv_bfloat16* __restrict__ Phi, __nv_bfloat16* __restrict__ Plo)
{
    const float* p = S + (size_t)blockIdx.x * NN;
    const int t = threadIdx.x;
    float v[8];
    float mx = -3.4e38f;
    #pragma unroll
    for (int i = 0; i < 8; i++) { v[i] = p[t + i * 256]; mx = fmaxf(mx, v[i]); }

    __shared__ float red[256];
    red[t] = mx; __syncthreads();
    #pragma unroll
    for (int s = 128; s > 0; s >>= 1) {
        if (t < s) red[t] = fmaxf(red[t], red[t + s]);
        __syncthreads();
    }
    mx = red[0];
    __syncthreads();

    float sum = 0.f;
    #pragma unroll
    for (int i = 0; i < 8; i++) { v[i] = __expf(v[i] - mx); sum += v[i]; }
    red[t] = sum; __syncthreads();
    #pragma unroll
    for (int s = 128; s > 0; s >>= 1) {
        if (t < s) red[t] += red[t + s];
        __syncthreads();
    }
    const float inv = 1.0f / red[0];
    __nv_bfloat16* ph = Phi + (size_t)blockIdx.x * NN;
    __nv_bfloat16* pl = Plo + (size_t)blockIdx.x * NN;
    #pragma unroll
    for (int i = 0; i < 8; i++) {
        const float pv = v[i] * inv;
        const __nv_bfloat16 hi = __float2bfloat16_rn(pv);
        const __nv_bfloat16 lo = __float2bfloat16_rn(pv - __bfloat162float(hi));
        ph[t + i * 256] = hi;
        pl[t + i * 256] = lo;
    }
}

// --------- out = h1 + h2 + e1^T B_w[o] e2 ----------------------------------
__global__ void __launch_bounds__(256)
final_k(const float* __restrict__ h1, const float* __restrict__ h2,
        const float* __restrict__ e1, const float* __restrict__ e2,
        const float* __restrict__ Bw, float* __restrict__ out)
{
    const int m = blockIdx.x;
    const int o = threadIdx.x;   // 0..255
    __shared__ float s1[8], s2[8];
    if (o < 5) { s1[o] = e1[m * 8 + o]; s2[o] = e2[m * 8 + o]; }
    __syncthreads();

    const float* bw = Bw + o * 25;
    float s = 0.f;
    #pragma unroll
    for (int i = 0; i < 5; i++) {
        const float ei = s1[i];
        #pragma unroll
        for (int j = 0; j < 5; j++) s += ei * bw[i * 5 + j] * s2[j];
    }
    const size_t idx = (size_t)m * FOUTx + o;
    out[idx] = h1[idx] + h2[idx] + s;
}

// ---------------------------------------------------------------------------
extern "C" void kernel_launch(void* const* d_in, const int* in_sizes, int n_in,
                              void* d_out, int out_size)
{
    const float* feat = (const float*)d_in[0];
    const int*   adj  = (const int*)  d_in[1];
    const float* W    = (const float*)d_in[2];
    const float* W1   = (const float*)d_in[3];
    const float* W2   = (const float*)d_in[4];
    const float* a1   = (const float*)d_in[5];
    const float* a2   = (const float*)d_in[6];
    const float* a12  = (const float*)d_in[7];
    const float* Lw   = (const float*)d_in[8];
    const float* Rw   = (const float*)d_in[9];
    const float* Bw   = (const float*)d_in[10];
    float* out = (float*)d_out;

    float *h, *h1, *g, *h2, *Ax, *Ay, *e1, *e2, *S, *fa;
    __nv_bfloat16 *Shi, *Slo, *Fhi, *Flo, *ghi, *glo, *hhi, *hlo;
    __nv_bfloat16 *fRhi, *fRlo, *fahi, *falo;
    __nv_bfloat16 *Wth, *Wtl, *W1th, *W1tl, *W2th, *W2tl, *a12th, *a12tl;
    cudaGetSymbolAddress((void**)&h,  g_h);
    cudaGetSymbolAddress((void**)&h1, g_h1);
    cudaGetSymbolAddress((void**)&g,  g_g);
    cudaGetSymbolAddress((void**)&h2, g_h2);
    cudaGetSymbolAddress((void**)&Ax, g_Ax);
    cudaGetSymbolAddress((void**)&Ay, g_Ay);
    cudaGetSymbolAddress((void**)&e1, g_e1);
    cudaGetSymbolAddress((void**)&e2, g_e2);
    cudaGetSymbolAddress((void**)&S,  g_S);
    cudaGetSymbolAddress((void**)&fa, g_fa);
    cudaGetSymbolAddress((void**)&Shi, g_Shi);
    cudaGetSymbolAddress((void**)&Slo, g_Slo);
    cudaGetSymbolAddress((void**)&Fhi, g_Fhi);
    cudaGetSymbolAddress((void**)&Flo, g_Flo);
    cudaGetSymbolAddress((void**)&ghi, g_ghi);
    cudaGetSymbolAddress((void**)&glo, g_glo);
    cudaGetSymbolAddress((void**)&hhi, g_hhi);
    cudaGetSymbolAddress((void**)&hlo, g_hlo);
    cudaGetSymbolAddress((void**)&fRhi, g_fRhi);
    cudaGetSymbolAddress((void**)&fRlo, g_fRlo);
    cudaGetSymbolAddress((void**)&fahi, g_fahi);
    cudaGetSymbolAddress((void**)&falo, g_falo);
    cudaGetSymbolAddress((void**)&Wth,  g_Wth);
    cudaGetSymbolAddress((void**)&Wtl,  g_Wtl);
    cudaGetSymbolAddress((void**)&W1th, g_W1th);
    cudaGetSymbolAddress((void**)&W1tl, g_W1tl);
    cudaGetSymbolAddress((void**)&W2th, g_W2th);
    cudaGetSymbolAddress((void**)&W2tl, g_W2tl);
    cudaGetSymbolAddress((void**)&a12th, g_a12th);
    cudaGetSymbolAddress((void**)&a12tl, g_a12tl);

    static int smem_set = 0;
    if (!smem_set) {
        cudaFuncSetAttribute(mma_gemm_k<0>, cudaFuncAttributeMaxDynamicSharedMemorySize,
                             AGG_SMEM);
        cudaFuncSetAttribute(mma_gemm_k<1>, cudaFuncAttributeMaxDynamicSharedMemorySize,
                             AGG_SMEM);
        smem_set = 1;
    }

    const dim3 blk(256);
    const dim3 tb(32, 8);

    // weight transposes + splits (tiny)
    tsplit_k<<<dim3(FOUTx/32, FINx/32), tb>>>(W,   Wth,  Wtl,  FINx,  FOUTx);
    tsplit_k<<<dim3(FOUTx/32, FINx/32), tb>>>(W1,  W1th, W1tl, FINx,  FOUTx);
    tsplit_k<<<dim3(FOUTx/32, FINx/32), tb>>>(W2,  W2th, W2tl, FINx,  FOUTx);
    tsplit_k<<<dim3(FOUTx/32, FOUTx/32), tb>>>(a12, a12th, a12tl, FOUTx, FOUTx);

    // feat splits: row-major (A operand) + transposed (B operand for agg)
    const size_t nfeat4 = (size_t)MTOT * FINx / 4;
    split_k<<<(unsigned)((nfeat4 + 255) / 256), 256>>>(feat, fRhi, fRlo, nfeat4);
    transpose_split_k<<<dim3(NN/32, FINx/32, Bn), tb>>>(feat, Fhi, Flo);

    // h = feat @ W ; h1 = feat @ W1   (HMMA)
    mma_gemm_k<0><<<dim3(FOUTx/128, MTOT/128, 1), blk, AGG_SMEM>>>(
        fRhi, fRlo, Wth, Wtl, h, FINx, MTOT, FOUTx, FOUTx, nullptr, nullptr, nullptr);
    mma_gemm_k<0><<<dim3(FOUTx/128, MTOT/128, 1), blk, AGG_SMEM>>>(
        fRhi, fRlo, W1th, W1tl, h1, FINx, MTOT, FOUTx, FOUTx, nullptr, nullptr, nullptr);

    // h split (operand for g and scores B)
    const size_t nh4 = (size_t)MTOT * FOUTx / 4;
    split_k<<<(unsigned)((nh4 + 255) / 256), 256>>>(h, hhi, hlo, nh4);

    // Ax, Ay, e1
    small1_k<<<MTOT/8, 256>>>(h, feat, a1, a2, Lw, Ax, Ay, e1);

    // g = h @ a12  (HMMA) ; then split
    mma_gemm_k<0><<<dim3(FOUTx/128, MTOT/128, 1), blk, AGG_SMEM>>>(
        hhi, hlo, a12th, a12tl, g, FOUTx, MTOT, FOUTx, FOUTx, nullptr, nullptr, nullptr);
    split_k<<<(unsigned)((nh4 + 255) / 256), 256>>>(g, ghi, glo, nh4);

    // S = leaky(Ax+Ay+g.h^T) masked  (HMMA)
    mma_gemm_k<1><<<dim3(NN/128, NN/128, Bn), blk, AGG_SMEM>>>(
        ghi, glo, hhi, hlo, S, FOUTx, NN, NN, NN, Ax, Ay, adj);

    // row softmax -> bf16 hi/lo probs
    softmax_k<<<MTOT, 256>>>(S, Shi, Slo);

    // feat_agg = P @ feat  (HMMA)
    mma_gemm_k<0><<<dim3(FINx/128, NN/128, Bn), blk, AGG_SMEM>>>(
        Shi, Slo, Fhi, Flo, fa, NN, NN, FINx, FINx, nullptr, nullptr, nullptr);

    // fa split ; h2 = fa @ W2 (HMMA) ; e2
    split_k<<<(unsigned)((nfeat4 + 255) / 256), 256>>>(fa, fahi, falo, nfeat4);
    mma_gemm_k<0><<<dim3(FOUTx/128, MTOT/128, 1), blk, AGG_SMEM>>>(
        fahi, falo, W2th, W2tl, h2, FINx, MTOT, FOUTx, FOUTx, nullptr, nullptr, nullptr);
    small2_k<<<MTOT/8, 256>>>(fa, Rw, e2);

    // out = h1 + h2 + bilinear(e1, B_w, e2)
    final_k<<<MTOT, 256>>>(h1, h2, e1, e2, Bw, out);
}